// round 2
// baseline (speedup 1.0000x reference)
#include <cuda_runtime.h>
#include <cuda_bf16.h>
#include <math.h>

// ---------------- problem constants ----------------
#define L_    4
#define B_    2
#define QLEN_ 512
#define MLEN_ 512
#define CLEN_ 1024
#define RLEN_ 1536
#define H_    1024
#define NH_   16
#define D_    64
#define F_    4096
#define LN_EPS_ 1e-12f

#define EFSTRIDE ((long long)B_*NH_*QLEN_)

// ---------------- scratch (device globals; no allocations allowed) ----------------
__device__ float g_x   [B_*QLEN_*H_];
__device__ float g_ctx [B_*CLEN_*H_];
__device__ float g_q   [B_*QLEN_*H_];
__device__ float g_qc  [B_*QLEN_*H_];
__device__ float g_qp  [B_*QLEN_*H_];
__device__ float g_k   [B_*CLEN_*H_];
__device__ float g_v   [B_*CLEN_*H_];
__device__ float g_r   [B_*RLEN_*H_];
__device__ float g_sc  [(long long)B_*NH_*QLEN_*CLEN_];   // scores -> probs (in place)
__device__ float g_bd  [(long long)B_*NH_*QLEN_*RLEN_];
__device__ float g_ef  [2*B_*NH_*QLEN_];
__device__ float g_attn[B_*QLEN_*H_];
__device__ float g_ao  [B_*QLEN_*H_];       // also reused for FFN output
__device__ float g_y   [B_*QLEN_*H_];
__device__ float g_mid [B_*QLEN_*F_];
__device__ int   g_segmode;   // 0=float32, 1=int32, 2=uint8

// ---------------- generic tiled GEMM ----------------
// C[M,N] = A[M,K] * B  (TB=0: B is [K,N]; TB=1: B is [N,K] -> C=A*B^T)
// optional per-column bias and relu. Batch via blockIdx.z decomposed as (outer, inner).
#define BM 64
#define BN 64
#define BK 16

template<int TB>
__global__ void __launch_bounds__(256)
gemm_k(const float* __restrict__ A, const float* __restrict__ Bm, float* __restrict__ C,
       int M, int N, int K, int lda, int ldb, int ldc,
       const float* __restrict__ bias, int relu,
       int inner,
       long long oAo, long long oAi, long long oBo, long long oBi,
       long long oCo, long long oCi)
{
    int z  = blockIdx.z;
    int zo = z / inner;
    int zi = z - zo * inner;
    A  += zo * oAo + zi * oAi;
    Bm += zo * oBo + zi * oBi;
    C  += zo * oCo + zi * oCi;

    __shared__ float As[BK][BM + 1];
    __shared__ float Bs[BK][BN + 1];

    int m0 = blockIdx.y * BM;
    int n0 = blockIdx.x * BN;
    int t  = threadIdx.x;
    int ty = t >> 4;          // 0..15
    int tx = t & 15;          // 0..15

    float acc[4][4];
#pragma unroll
    for (int u = 0; u < 4; u++)
#pragma unroll
        for (int v = 0; v < 4; v++) acc[u][v] = 0.f;

    for (int k0 = 0; k0 < K; k0 += BK) {
        // --- load A tile (64 rows x 16 k) ---
        {
            int m  = t >> 2;           // 0..63
            int kk = (t & 3) << 2;     // 0,4,8,12
            int gm = m0 + m;
#pragma unroll
            for (int j = 0; j < 4; j++) {
                int gk  = k0 + kk + j;
                float v = (gm < M && gk < K) ? A[(long long)gm * lda + gk] : 0.f;
                As[kk + j][m] = v;
            }
        }
        // --- load B tile ---
        if (TB == 0) {
            int kk = t >> 4;           // 0..15
            int nn = (t & 15) << 2;    // 0..60
            int gk = k0 + kk;
#pragma unroll
            for (int j = 0; j < 4; j++) {
                int gn  = n0 + nn + j;
                float v = (gk < K && gn < N) ? Bm[(long long)gk * ldb + gn] : 0.f;
                Bs[kk][nn + j] = v;
            }
        } else {
            int n  = t >> 2;           // 0..63
            int kk = (t & 3) << 2;
            int gn = n0 + n;
#pragma unroll
            for (int j = 0; j < 4; j++) {
                int gk  = k0 + kk + j;
                float v = (gn < N && gk < K) ? Bm[(long long)gn * ldb + gk] : 0.f;
                Bs[kk + j][n] = v;
            }
        }
        __syncthreads();

#pragma unroll
        for (int k = 0; k < BK; k++) {
            float a[4], b[4];
#pragma unroll
            for (int u = 0; u < 4; u++) a[u] = As[k][ty * 4 + u];
#pragma unroll
            for (int v = 0; v < 4; v++) b[v] = Bs[k][tx * 4 + v];
#pragma unroll
            for (int u = 0; u < 4; u++)
#pragma unroll
                for (int v = 0; v < 4; v++)
                    acc[u][v] = fmaf(a[u], b[v], acc[u][v]);
        }
        __syncthreads();
    }

#pragma unroll
    for (int u = 0; u < 4; u++) {
        int gm = m0 + ty * 4 + u;
        if (gm >= M) continue;
#pragma unroll
        for (int v = 0; v < 4; v++) {
            int gn = n0 + tx * 4 + v;
            if (gn >= N) continue;
            float val = acc[u][v];
            if (bias) val += bias[gn];
            if (relu) val = fmaxf(val, 0.f);
            C[(long long)gm * ldc + gn] = val;
        }
    }
}

static void launch_gemm(bool transB,
                        const float* A, const float* Bm, float* C,
                        int M, int N, int K, int lda, int ldb, int ldc,
                        const float* bias, int relu,
                        int batches, int inner,
                        long long oAo, long long oAi,
                        long long oBo, long long oBi,
                        long long oCo, long long oCi)
{
    dim3 grid((N + BN - 1) / BN, (M + BM - 1) / BM, batches);
    if (transB)
        gemm_k<1><<<grid, 256>>>(A, Bm, C, M, N, K, lda, ldb, ldc, bias, relu,
                                 inner, oAo, oAi, oBo, oBi, oCo, oCi);
    else
        gemm_k<0><<<grid, 256>>>(A, Bm, C, M, N, K, lda, ldb, ldc, bias, relu,
                                 inner, oAo, oAi, oBo, oBi, oCo, oCi);
}

// ---------------- small kernels ----------------

// detect segment_matrix storage dtype by byte pattern of first 1024 bytes
__global__ void detect_seg_kernel(const unsigned char* __restrict__ p)
{
    if (threadIdx.x == 0 && blockIdx.x == 0) {
        bool f32 = false, nonalign = false;
        for (int i = 0; i < 1024; i++) {
            unsigned char c = p[i];
            if ((i & 3) == 3 && c == 0x3F) f32 = true;       // 1.0f high byte
            if ((i & 3) != 0 && c == 1)    nonalign = true;  // packed uint8 ones
        }
        g_segmode = f32 ? 0 : (nonalign ? 2 : 1);
    }
}

// ctx[b, j, h] = j < MLEN ? mems_l[b,j,h] : x[b, j-MLEN, h]
__global__ void build_ctx_kernel(const float* __restrict__ mems_l,
                                 const float* __restrict__ x)
{
    int idx = blockIdx.x * blockDim.x + threadIdx.x;
    if (idx >= B_ * CLEN_ * H_) return;
    int h = idx % H_;
    int j = (idx / H_) % CLEN_;
    int b = idx / (H_ * CLEN_);
    float v = (j < MLEN_) ? mems_l[((long long)b * MLEN_ + j) * H_ + h]
                          : x[((long long)b * QLEN_ + (j - MLEN_)) * H_ + h];
    g_ctx[idx] = v;
}

// qc = q + content_bias, qp = q + position_bias (bias indexed by nd = idx % H)
__global__ void make_qcp_kernel(const float* __restrict__ cb,
                                const float* __restrict__ pb)
{
    int idx = blockIdx.x * blockDim.x + threadIdx.x;
    if (idx >= B_ * QLEN_ * H_) return;
    int nd  = idx % H_;
    float q = g_q[idx];
    g_qc[idx] = q + cb[nd];
    g_qp[idx] = q + pb[nd];
}

// ef[s][b,n,i] = sum_d (q[b,i,n,d] + sb[n,d]) * se_l[s,n,d]
__global__ void ef_kernel(const float* __restrict__ sb,
                          const float* __restrict__ se_l)
{
    int bi   = blockIdx.x;             // b*QLEN + i
    int n    = threadIdx.x >> 5;       // head (16 warps)
    int lane = threadIdx.x & 31;
    const float* qrow = g_q + (long long)bi * H_ + n * D_;
    float s0 = 0.f, s1 = 0.f;
#pragma unroll
    for (int d = lane; d < D_; d += 32) {
        float qv = qrow[d] + sb[n * D_ + d];
        s0 += qv * se_l[n * D_ + d];
        s1 += qv * se_l[NH_ * D_ + n * D_ + d];
    }
#pragma unroll
    for (int o = 16; o > 0; o >>= 1) {
        s0 += __shfl_down_sync(0xFFFFFFFFu, s0, o);
        s1 += __shfl_down_sync(0xFFFFFFFFu, s1, o);
    }
    if (lane == 0) {
        int b = bi / QLEN_;
        int i = bi - b * QLEN_;
        long long ridx = ((long long)(b * NH_ + n) * QLEN_ + i);
        g_ef[ridx]            = s0;
        g_ef[EFSTRIDE + ridx] = s1;
    }
}

// fused: scores = (ac + bd_shifted + ef)/8 + mask*(-1e30); softmax over j; probs in-place
__global__ void __launch_bounds__(256)
score_softmax_kernel(const float* __restrict__ mask, const void* __restrict__ seg)
{
    int row = blockIdx.x;               // over B*NH*QLEN
    int i   = row % QLEN_;
    int bn  = row / QLEN_;
    int b   = bn / NH_;
    int tid = threadIdx.x;

    float*       ac   = g_sc + (long long)bn * QLEN_ * CLEN_ + (long long)i * CLEN_;
    const float* bd   = g_bd + (long long)bn * QLEN_ * RLEN_ + (long long)i * RLEN_ + (QLEN_ - i);
    const float* mrow = mask + ((long long)b * QLEN_ + i) * CLEN_;
    long long    sbase = ((long long)b * QLEN_ + i) * (long long)CLEN_;
    float ef0 = g_ef[(long long)bn * QLEN_ + i];
    float ef1 = g_ef[EFSTRIDE + (long long)bn * QLEN_ + i];
    int mode = g_segmode;
    const float rs = 0.125f;

    float vals[4];
    float lmax = -3.0e38f;
#pragma unroll
    for (int u = 0; u < 4; u++) {
        int j = u * 256 + tid;
        bool s;
        if (mode == 2)      s = ((const unsigned char*)seg)[sbase + j] != 0;
        else if (mode == 1) s = ((const int*)seg)[sbase + j] != 0;
        else                s = ((const float*)seg)[sbase + j] != 0.f;
        float ef = s ? ef1 : ef0;
        float sc = (ac[j] + bd[j] + ef) * rs + mrow[j] * (-1e30f);
        vals[u] = sc;
        lmax = fmaxf(lmax, sc);
    }

    __shared__ float red[256];
    red[tid] = lmax;
    __syncthreads();
    for (int o = 128; o > 0; o >>= 1) {
        if (tid < o) red[tid] = fmaxf(red[tid], red[tid + o]);
        __syncthreads();
    }
    float m = red[0];
    __syncthreads();

    float lsum = 0.f;
#pragma unroll
    for (int u = 0; u < 4; u++) {
        vals[u] = __expf(vals[u] - m);
        lsum += vals[u];
    }
    red[tid] = lsum;
    __syncthreads();
    for (int o = 128; o > 0; o >>= 1) {
        if (tid < o) red[tid] += red[tid + o];
        __syncthreads();
    }
    float inv = 1.f / red[0];
#pragma unroll
    for (int u = 0; u < 4; u++) {
        int j = u * 256 + tid;
        ac[j] = vals[u] * inv;
    }
}

// out = LN(a + b) * gamma + beta   (row = one token, H=1024)
__global__ void __launch_bounds__(256)
ln_kernel(const float* __restrict__ a, const float* __restrict__ b,
          const float* __restrict__ gamma, const float* __restrict__ beta,
          float* __restrict__ out)
{
    int row = blockIdx.x;
    int tid = threadIdx.x;
    const float* pa = a + (long long)row * H_;
    const float* pb = b + (long long)row * H_;

    float v[4];
    float lsum = 0.f;
#pragma unroll
    for (int u = 0; u < 4; u++) {
        int j = u * 256 + tid;
        v[u] = pa[j] + pb[j];
        lsum += v[u];
    }
    __shared__ float red[256];
    red[tid] = lsum;
    __syncthreads();
    for (int o = 128; o > 0; o >>= 1) {
        if (tid < o) red[tid] += red[tid + o];
        __syncthreads();
    }
    float mu = red[0] * (1.0f / H_);
    __syncthreads();

    float lvar = 0.f;
#pragma unroll
    for (int u = 0; u < 4; u++) {
        float d = v[u] - mu;
        lvar += d * d;
    }
    red[tid] = lvar;
    __syncthreads();
    for (int o = 128; o > 0; o >>= 1) {
        if (tid < o) red[tid] += red[tid + o];
        __syncthreads();
    }
    float rstd = rsqrtf(red[0] * (1.0f / H_) + LN_EPS_);
    float* po = out + (long long)row * H_;
#pragma unroll
    for (int u = 0; u < 4; u++) {
        int j = u * 256 + tid;
        po[j] = (v[u] - mu) * rstd * gamma[j] + beta[j];
    }
}

// ---------------- host orchestration ----------------
struct ScratchPtrs {
    float *x, *ctx, *q, *qc, *qp, *k, *v, *r, *sc, *bd, *attn, *ao, *y, *mid;
    bool init = false;
};

extern "C" void kernel_launch(void* const* d_in, const int* in_sizes, int n_in,
                              void* d_out, int out_size)
{
    (void)in_sizes; (void)n_in; (void)out_size;

    const float* content   = (const float*)d_in[0];
    const float* mask      = (const float*)d_in[1];
    const float* posenc    = (const float*)d_in[2];
    const void*  seg       = d_in[3];
    const float* mems      = (const float*)d_in[4];
    const float* w_q       = (const float*)d_in[5];
    const float* w_k       = (const float*)d_in[6];
    const float* w_v       = (const float*)d_in[7];
    const float* w_r       = (const float*)d_in[8];
    const float* w_o       = (const float*)d_in[9];
    const float* ffn_w1    = (const float*)d_in[10];
    const float* ffn_b1    = (const float*)d_in[11];
    const float* ffn_w2    = (const float*)d_in[12];
    const float* ffn_b2    = (const float*)d_in[13];
    const float* ln1_g     = (const float*)d_in[14];
    const float* ln1_b     = (const float*)d_in[15];
    const float* ln2_g     = (const float*)d_in[16];
    const float* ln2_b     = (const float*)d_in[17];
    const float* cbias     = (const float*)d_in[18];
    const float* pbias     = (const float*)d_in[19];
    const float* sbias     = (const float*)d_in[20];
    const float* segenc    = (const float*)d_in[21];

    static ScratchPtrs S;
    if (!S.init) {
        cudaGetSymbolAddress((void**)&S.x,    g_x);
        cudaGetSymbolAddress((void**)&S.ctx,  g_ctx);
        cudaGetSymbolAddress((void**)&S.q,    g_q);
        cudaGetSymbolAddress((void**)&S.qc,   g_qc);
        cudaGetSymbolAddress((void**)&S.qp,   g_qp);
        cudaGetSymbolAddress((void**)&S.k,    g_k);
        cudaGetSymbolAddress((void**)&S.v,    g_v);
        cudaGetSymbolAddress((void**)&S.r,    g_r);
        cudaGetSymbolAddress((void**)&S.sc,   g_sc);
        cudaGetSymbolAddress((void**)&S.bd,   g_bd);
        cudaGetSymbolAddress((void**)&S.attn, g_attn);
        cudaGetSymbolAddress((void**)&S.ao,   g_ao);
        cudaGetSymbolAddress((void**)&S.y,    g_y);
        cudaGetSymbolAddress((void**)&S.mid,  g_mid);
        S.init = true;
    }

    detect_seg_kernel<<<1, 32>>>((const unsigned char*)seg);

    const float* x = content;
    const int rowsQ = B_ * QLEN_;   // 1024
    const int rowsC = B_ * CLEN_;   // 2048
    const int rowsR = B_ * RLEN_;   // 3072

    for (int l = 0; l < L_; l++) {
        long long wofs = (long long)l * H_ * H_;

        // context = concat(mems[l], x)
        {
            int total = B_ * CLEN_ * H_;
            build_ctx_kernel<<<(total + 255) / 256, 256>>>(
                mems + (long long)l * B_ * MLEN_ * H_, x);
        }

        // projections
        launch_gemm(false, x,      w_q + wofs, S.q, rowsQ, H_, H_, H_, H_, H_,
                    nullptr, 0, 1, 1, 0,0,0,0,0,0);
        launch_gemm(false, S.ctx,  w_k + wofs, S.k, rowsC, H_, H_, H_, H_, H_,
                    nullptr, 0, 1, 1, 0,0,0,0,0,0);
        launch_gemm(false, S.ctx,  w_v + wofs, S.v, rowsC, H_, H_, H_, H_, H_,
                    nullptr, 0, 1, 1, 0,0,0,0,0,0);
        launch_gemm(false, posenc, w_r + wofs, S.r, rowsR, H_, H_, H_, H_, H_,
                    nullptr, 0, 1, 1, 0,0,0,0,0,0);

        // q + biases; segment dots
        {
            int total = B_ * QLEN_ * H_;
            make_qcp_kernel<<<(total + 255) / 256, 256>>>(cbias, pbias);
        }
        ef_kernel<<<B_ * QLEN_, 512>>>(sbias, segenc + (long long)l * 2 * NH_ * D_);

        // ac[b,n]: (512x64) x (1024x64)^T  -> scores buffer
        launch_gemm(true, S.qc, S.k, S.sc,
                    QLEN_, CLEN_, D_, H_, H_, CLEN_,
                    nullptr, 0,
                    B_ * NH_, NH_,
                    (long long)QLEN_ * H_, D_,
                    (long long)CLEN_ * H_, D_,
                    (long long)NH_ * QLEN_ * CLEN_, (long long)QLEN_ * CLEN_);

        // bd[b,n]: (512x64) x (1536x64)^T -> bd buffer
        launch_gemm(true, S.qp, S.r, S.bd,
                    QLEN_, RLEN_, D_, H_, H_, RLEN_,
                    nullptr, 0,
                    B_ * NH_, NH_,
                    (long long)QLEN_ * H_, D_,
                    (long long)RLEN_ * H_, D_,
                    (long long)NH_ * QLEN_ * RLEN_, (long long)QLEN_ * RLEN_);

        // fused scores + rel-shift + segment + mask + softmax (in place -> probs)
        score_softmax_kernel<<<B_ * NH_ * QLEN_, 256>>>(mask, seg);

        // attn[b,n] = probs (512x1024) x V (1024x64)
        launch_gemm(false, S.sc, S.v, S.attn,
                    QLEN_, D_, CLEN_, CLEN_, H_, H_,
                    nullptr, 0,
                    B_ * NH_, NH_,
                    (long long)NH_ * QLEN_ * CLEN_, (long long)QLEN_ * CLEN_,
                    (long long)CLEN_ * H_, D_,
                    (long long)QLEN_ * H_, D_);

        // attn_out = attn [1024 x 1024] * w_o^T
        launch_gemm(true, S.attn, w_o + wofs, S.ao,
                    rowsQ, H_, H_, H_, H_, H_,
                    nullptr, 0, 1, 1, 0,0,0,0,0,0);

        // y = LN1(attn_out + x)
        ln_kernel<<<rowsQ, 256>>>(S.ao, x, ln1_g + l * H_, ln1_b + l * H_, S.y);

        // FFN (mid = relu(y*W1+b1); ao reused = mid*W2+b2)
        launch_gemm(false, S.y,   ffn_w1 + (long long)l * H_ * F_, S.mid,
                    rowsQ, F_, H_, H_, F_, F_,
                    ffn_b1 + (long long)l * F_, 1, 1, 1, 0,0,0,0,0,0);
        launch_gemm(false, S.mid, ffn_w2 + (long long)l * F_ * H_, S.ao,
                    rowsQ, H_, F_, F_, H_, H_,
                    ffn_b2 + (long long)l * H_, 0, 1, 1, 0,0,0,0,0,0);

        // x_next = LN2(ffn + y)
        float* xout = (l == L_ - 1) ? (float*)d_out : S.x;
        ln_kernel<<<rowsQ, 256>>>(S.ao, S.y, ln2_g + l * H_, ln2_b + l * H_, xout);

        x = S.x;
    }
}

// round 6
// speedup vs baseline: 1.2674x; 1.2674x over previous
#include <cuda_runtime.h>
#include <cuda_bf16.h>
#include <math.h>

// ---------------- problem constants ----------------
#define L_    4
#define B_    2
#define QLEN_ 512
#define MLEN_ 512
#define CLEN_ 1024
#define RLEN_ 1536
#define H_    1024
#define NH_   16
#define D_    64
#define F_    4096
#define LN_EPS_ 1e-12f

#define EFSTRIDE ((long long)B_*NH_*QLEN_)

// ---------------- scratch (device globals; no allocations allowed) ----------------
__device__ float g_x   [B_*QLEN_*H_];
__device__ float g_ctx [B_*CLEN_*H_];
__device__ float g_q   [B_*QLEN_*H_];
__device__ float g_qc  [B_*QLEN_*H_];
__device__ float g_qp  [B_*QLEN_*H_];
__device__ float g_k   [B_*CLEN_*H_];
__device__ float g_v   [B_*CLEN_*H_];
__device__ float g_r   [B_*RLEN_*H_];
__device__ float g_sc  [(long long)B_*NH_*QLEN_*CLEN_];   // scores -> probs (in place)
__device__ float g_bd  [(long long)B_*NH_*QLEN_*RLEN_];
__device__ float g_ef  [2*B_*NH_*QLEN_];
__device__ float g_attn[B_*QLEN_*H_];
__device__ float g_ao  [B_*QLEN_*H_];       // also reused for FFN output
__device__ float g_y   [B_*QLEN_*H_];
__device__ float g_mid [B_*QLEN_*F_];
__device__ int   g_segmode;   // 0=float32, 1=int32, 2=uint8

// ---------------- high-intensity tiled GEMM ----------------
// C[M,N] = A[M,K] * B  (TB=0: B is [K,N]; TB=1: B is [N,K] -> C=A*B^T)
// 128x128 tile, BK=8, 256 threads, 8x8 per thread, float4 smem, double buffer.
// Requires K % 8 == 0, lda/ldb/ldc % 4 == 0, pointers 16B aligned (true here).
#define TM 128
#define TN 128
#define TK 8
#define SPAD 132   // row stride in floats (128 + 4 pad), keeps 16B alignment

template<int TB>
__global__ void __launch_bounds__(256)
gemm_k(const float* __restrict__ A, const float* __restrict__ Bm, float* __restrict__ C,
       int M, int N, int K, int lda, int ldb, int ldc,
       const float* __restrict__ bias, int relu,
       int inner,
       long long oAo, long long oAi, long long oBo, long long oBi,
       long long oCo, long long oCi)
{
    int z  = blockIdx.z;
    int zo = z / inner;
    int zi = z - zo * inner;
    A  += zo * oAo + zi * oAi;
    Bm += zo * oBo + zi * oBi;
    C  += zo * oCo + zi * oCi;

    __shared__ float As[2][TK][SPAD];
    __shared__ float Bs[2][TK][SPAD];

    const int t  = threadIdx.x;
    const int m0 = blockIdx.y * TM;
    const int n0 = blockIdx.x * TN;

    // A tile loader: thread -> (row am in [0,128), k-quad ak in {0,4})
    const int am = t & 127;
    const int ak = (t >> 7) << 2;
    // B tile loader
    const int bk  = t >> 5;          // TB==0: k row 0..7
    const int bn  = (t & 31) << 2;   // TB==0: n quad 0..124
    const int bn2 = t & 127;         // TB==1: n row
    const int bkk = (t >> 7) << 2;   // TB==1: k quad

    // compute-side fragment coords
    const int tx4 = (t & 15) << 2;
    const int ty4 = (t >> 4) << 2;

    float acc[8][8];
#pragma unroll
    for (int u = 0; u < 8; u++)
#pragma unroll
        for (int v = 0; v < 8; v++) acc[u][v] = 0.f;

    auto loadA = [&](int k0) -> float4 {
        int gm = m0 + am, gk = k0 + ak;
        if (gm < M && gk < K)
            return *reinterpret_cast<const float4*>(A + (long long)gm * lda + gk);
        return make_float4(0.f, 0.f, 0.f, 0.f);
    };
    auto loadB = [&](int k0) -> float4 {
        if (TB == 0) {
            int gk = k0 + bk, gn = n0 + bn;
            if (gk < K && gn < N)
                return *reinterpret_cast<const float4*>(Bm + (long long)gk * ldb + gn);
        } else {
            int gn = n0 + bn2, gk = k0 + bkk;
            if (gn < N && gk < K)
                return *reinterpret_cast<const float4*>(Bm + (long long)gn * ldb + gk);
        }
        return make_float4(0.f, 0.f, 0.f, 0.f);
    };
    auto storeTiles = [&](int buf, float4 a, float4 b) {
        As[buf][ak + 0][am] = a.x;
        As[buf][ak + 1][am] = a.y;
        As[buf][ak + 2][am] = a.z;
        As[buf][ak + 3][am] = a.w;
        if (TB == 0) {
            *reinterpret_cast<float4*>(&Bs[buf][bk][bn]) = b;
        } else {
            Bs[buf][bkk + 0][bn2] = b.x;
            Bs[buf][bkk + 1][bn2] = b.y;
            Bs[buf][bkk + 2][bn2] = b.z;
            Bs[buf][bkk + 3][bn2] = b.w;
        }
    };

    // prologue
    {
        float4 a = loadA(0), b = loadB(0);
        storeTiles(0, a, b);
    }
    __syncthreads();

    int buf = 0;
    for (int k0 = TK; k0 < K; k0 += TK) {
        float4 aP = loadA(k0);
        float4 bP = loadB(k0);

#pragma unroll
        for (int k = 0; k < TK; k++) {
            float4 a0 = *reinterpret_cast<const float4*>(&As[buf][k][ty4]);
            float4 a1 = *reinterpret_cast<const float4*>(&As[buf][k][ty4 + 64]);
            float4 b0 = *reinterpret_cast<const float4*>(&Bs[buf][k][tx4]);
            float4 b1 = *reinterpret_cast<const float4*>(&Bs[buf][k][tx4 + 64]);
            float af[8] = {a0.x, a0.y, a0.z, a0.w, a1.x, a1.y, a1.z, a1.w};
            float bf[8] = {b0.x, b0.y, b0.z, b0.w, b1.x, b1.y, b1.z, b1.w};
#pragma unroll
            for (int u = 0; u < 8; u++)
#pragma unroll
                for (int v = 0; v < 8; v++)
                    acc[u][v] = fmaf(af[u], bf[v], acc[u][v]);
        }

        storeTiles(buf ^ 1, aP, bP);
        __syncthreads();
        buf ^= 1;
    }

    // last tile
#pragma unroll
    for (int k = 0; k < TK; k++) {
        float4 a0 = *reinterpret_cast<const float4*>(&As[buf][k][ty4]);
        float4 a1 = *reinterpret_cast<const float4*>(&As[buf][k][ty4 + 64]);
        float4 b0 = *reinterpret_cast<const float4*>(&Bs[buf][k][tx4]);
        float4 b1 = *reinterpret_cast<const float4*>(&Bs[buf][k][tx4 + 64]);
        float af[8] = {a0.x, a0.y, a0.z, a0.w, a1.x, a1.y, a1.z, a1.w};
        float bf[8] = {b0.x, b0.y, b0.z, b0.w, b1.x, b1.y, b1.z, b1.w};
#pragma unroll
        for (int u = 0; u < 8; u++)
#pragma unroll
            for (int v = 0; v < 8; v++)
                acc[u][v] = fmaf(af[u], bf[v], acc[u][v]);
    }

    // epilogue
#pragma unroll
    for (int u = 0; u < 8; u++) {
        int gm = m0 + ((u < 4) ? (ty4 + u) : (ty4 + 64 + u - 4));
        if (gm >= M) continue;
        float* crow = C + (long long)gm * ldc;
#pragma unroll
        for (int v = 0; v < 8; v++) {
            int gn = n0 + ((v < 4) ? (tx4 + v) : (tx4 + 64 + v - 4));
            if (gn >= N) continue;
            float val = acc[u][v];
            if (bias) val += bias[gn];
            if (relu) val = fmaxf(val, 0.f);
            crow[gn] = val;
        }
    }
}

static void launch_gemm(bool transB,
                        const float* A, const float* Bm, float* C,
                        int M, int N, int K, int lda, int ldb, int ldc,
                        const float* bias, int relu,
                        int batches, int inner,
                        long long oAo, long long oAi,
                        long long oBo, long long oBi,
                        long long oCo, long long oCi)
{
    dim3 grid((N + TN - 1) / TN, (M + TM - 1) / TM, batches);
    if (transB)
        gemm_k<1><<<grid, 256>>>(A, Bm, C, M, N, K, lda, ldb, ldc, bias, relu,
                                 inner, oAo, oAi, oBo, oBi, oCo, oCi);
    else
        gemm_k<0><<<grid, 256>>>(A, Bm, C, M, N, K, lda, ldb, ldc, bias, relu,
                                 inner, oAo, oAi, oBo, oBi, oCo, oCi);
}

// ---------------- small kernels ----------------

// detect segment_matrix storage dtype by byte pattern of first 1024 bytes
__global__ void detect_seg_kernel(const unsigned char* __restrict__ p)
{
    if (threadIdx.x == 0 && blockIdx.x == 0) {
        bool f32 = false, nonalign = false;
        for (int i = 0; i < 1024; i++) {
            unsigned char c = p[i];
            if ((i & 3) == 3 && c == 0x3F) f32 = true;       // 1.0f high byte
            if ((i & 3) != 0 && c == 1)    nonalign = true;  // packed uint8 ones
        }
        g_segmode = f32 ? 0 : (nonalign ? 2 : 1);
    }
}

// ctx[b, j, h] = j < MLEN ? mems_l[b,j,h] : x[b, j-MLEN, h]
__global__ void build_ctx_kernel(const float* __restrict__ mems_l,
                                 const float* __restrict__ x)
{
    int idx = blockIdx.x * blockDim.x + threadIdx.x;
    if (idx >= B_ * CLEN_ * H_) return;
    int h = idx % H_;
    int j = (idx / H_) % CLEN_;
    int b = idx / (H_ * CLEN_);
    float v = (j < MLEN_) ? mems_l[((long long)b * MLEN_ + j) * H_ + h]
                          : x[((long long)b * QLEN_ + (j - MLEN_)) * H_ + h];
    g_ctx[idx] = v;
}

// qc = q + content_bias, qp = q + position_bias (bias indexed by nd = idx % H)
__global__ void make_qcp_kernel(const float* __restrict__ cb,
                                const float* __restrict__ pb)
{
    int idx = blockIdx.x * blockDim.x + threadIdx.x;
    if (idx >= B_ * QLEN_ * H_) return;
    int nd  = idx % H_;
    float q = g_q[idx];
    g_qc[idx] = q + cb[nd];
    g_qp[idx] = q + pb[nd];
}

// ef[s][b,n,i] = sum_d (q[b,i,n,d] + sb[n,d]) * se_l[s,n,d]
__global__ void ef_kernel(const float* __restrict__ sb,
                          const float* __restrict__ se_l)
{
    int bi   = blockIdx.x;             // b*QLEN + i
    int n    = threadIdx.x >> 5;       // head (16 warps)
    int lane = threadIdx.x & 31;
    const float* qrow = g_q + (long long)bi * H_ + n * D_;
    float s0 = 0.f, s1 = 0.f;
#pragma unroll
    for (int d = lane; d < D_; d += 32) {
        float qv = qrow[d] + sb[n * D_ + d];
        s0 += qv * se_l[n * D_ + d];
        s1 += qv * se_l[NH_ * D_ + n * D_ + d];
    }
#pragma unroll
    for (int o = 16; o > 0; o >>= 1) {
        s0 += __shfl_down_sync(0xFFFFFFFFu, s0, o);
        s1 += __shfl_down_sync(0xFFFFFFFFu, s1, o);
    }
    if (lane == 0) {
        int b = bi / QLEN_;
        int i = bi - b * QLEN_;
        long long ridx = ((long long)(b * NH_ + n) * QLEN_ + i);
        g_ef[ridx]            = s0;
        g_ef[EFSTRIDE + ridx] = s1;
    }
}

// fused: scores = (ac + bd_shifted + ef)/8 + mask*(-1e30); softmax over j; probs in-place
__global__ void __launch_bounds__(256)
score_softmax_kernel(const float* __restrict__ mask, const void* __restrict__ seg)
{
    int row = blockIdx.x;               // over B*NH*QLEN
    int i   = row % QLEN_;
    int bn  = row / QLEN_;
    int b   = bn / NH_;
    int tid = threadIdx.x;

    float*       ac   = g_sc + (long long)bn * QLEN_ * CLEN_ + (long long)i * CLEN_;
    const float* bd   = g_bd + (long long)bn * QLEN_ * RLEN_ + (long long)i * RLEN_ + (QLEN_ - i);
    const float* mrow = mask + ((long long)b * QLEN_ + i) * CLEN_;
    long long    sbase = ((long long)b * QLEN_ + i) * (long long)CLEN_;
    float ef0 = g_ef[(long long)bn * QLEN_ + i];
    float ef1 = g_ef[EFSTRIDE + (long long)bn * QLEN_ + i];
    int mode = g_segmode;
    const float rs = 0.125f;

    float vals[4];
    float lmax = -3.0e38f;
#pragma unroll
    for (int u = 0; u < 4; u++) {
        int j = u * 256 + tid;
        bool s;
        if (mode == 2)      s = ((const unsigned char*)seg)[sbase + j] != 0;
        else if (mode == 1) s = ((const int*)seg)[sbase + j] != 0;
        else                s = ((const float*)seg)[sbase + j] != 0.f;
        float ef = s ? ef1 : ef0;
        float sc = (ac[j] + bd[j] + ef) * rs + mrow[j] * (-1e30f);
        vals[u] = sc;
        lmax = fmaxf(lmax, sc);
    }

    __shared__ float red[256];
    red[tid] = lmax;
    __syncthreads();
    for (int o = 128; o > 0; o >>= 1) {
        if (tid < o) red[tid] = fmaxf(red[tid], red[tid + o]);
        __syncthreads();
    }
    float m = red[0];
    __syncthreads();

    float lsum = 0.f;
#pragma unroll
    for (int u = 0; u < 4; u++) {
        vals[u] = __expf(vals[u] - m);
        lsum += vals[u];
    }
    red[tid] = lsum;
    __syncthreads();
    for (int o = 128; o > 0; o >>= 1) {
        if (tid < o) red[tid] += red[tid + o];
        __syncthreads();
    }
    float inv = 1.f / red[0];
#pragma unroll
    for (int u = 0; u < 4; u++) {
        int j = u * 256 + tid;
        ac[j] = vals[u] * inv;
    }
}

// out = LN(a + b) * gamma + beta   (row = one token, H=1024)
__global__ void __launch_bounds__(256)
ln_kernel(const float* __restrict__ a, const float* __restrict__ b,
          const float* __restrict__ gamma, const float* __restrict__ beta,
          float* __restrict__ out)
{
    int row = blockIdx.x;
    int tid = threadIdx.x;
    const float* pa = a + (long long)row * H_;
    const float* pb = b + (long long)row * H_;

    float v[4];
    float lsum = 0.f;
#pragma unroll
    for (int u = 0; u < 4; u++) {
        int j = u * 256 + tid;
        v[u] = pa[j] + pb[j];
        lsum += v[u];
    }
    __shared__ float red[256];
    red[tid] = lsum;
    __syncthreads();
    for (int o = 128; o > 0; o >>= 1) {
        if (tid < o) red[tid] += red[tid + o];
        __syncthreads();
    }
    float mu = red[0] * (1.0f / H_);
    __syncthreads();

    float lvar = 0.f;
#pragma unroll
    for (int u = 0; u < 4; u++) {
        float d = v[u] - mu;
        lvar += d * d;
    }
    red[tid] = lvar;
    __syncthreads();
    for (int o = 128; o > 0; o >>= 1) {
        if (tid < o) red[tid] += red[tid + o];
        __syncthreads();
    }
    float rstd = rsqrtf(red[0] * (1.0f / H_) + LN_EPS_);
    float* po = out + (long long)row * H_;
#pragma unroll
    for (int u = 0; u < 4; u++) {
        int j = u * 256 + tid;
        po[j] = (v[u] - mu) * rstd * gamma[j] + beta[j];
    }
}

// ---------------- host orchestration ----------------
struct ScratchPtrs {
    float *x, *ctx, *q, *qc, *qp, *k, *v, *r, *sc, *bd, *attn, *ao, *y, *mid;
    bool init = false;
};

extern "C" void kernel_launch(void* const* d_in, const int* in_sizes, int n_in,
                              void* d_out, int out_size)
{
    (void)in_sizes; (void)n_in; (void)out_size;

    const float* content   = (const float*)d_in[0];
    const float* mask      = (const float*)d_in[1];
    const float* posenc    = (const float*)d_in[2];
    const void*  seg       = d_in[3];
    const float* mems      = (const float*)d_in[4];
    const float* w_q       = (const float*)d_in[5];
    const float* w_k       = (const float*)d_in[6];
    const float* w_v       = (const float*)d_in[7];
    const float* w_r       = (const float*)d_in[8];
    const float* w_o       = (const float*)d_in[9];
    const float* ffn_w1    = (const float*)d_in[10];
    const float* ffn_b1    = (const float*)d_in[11];
    const float* ffn_w2    = (const float*)d_in[12];
    const float* ffn_b2    = (const float*)d_in[13];
    const float* ln1_g     = (const float*)d_in[14];
    const float* ln1_b     = (const float*)d_in[15];
    const float* ln2_g     = (const float*)d_in[16];
    const float* ln2_b     = (const float*)d_in[17];
    const float* cbias     = (const float*)d_in[18];
    const float* pbias     = (const float*)d_in[19];
    const float* sbias     = (const float*)d_in[20];
    const float* segenc    = (const float*)d_in[21];

    static ScratchPtrs S;
    if (!S.init) {
        cudaGetSymbolAddress((void**)&S.x,    g_x);
        cudaGetSymbolAddress((void**)&S.ctx,  g_ctx);
        cudaGetSymbolAddress((void**)&S.q,    g_q);
        cudaGetSymbolAddress((void**)&S.qc,   g_qc);
        cudaGetSymbolAddress((void**)&S.qp,   g_qp);
        cudaGetSymbolAddress((void**)&S.k,    g_k);
        cudaGetSymbolAddress((void**)&S.v,    g_v);
        cudaGetSymbolAddress((void**)&S.r,    g_r);
        cudaGetSymbolAddress((void**)&S.sc,   g_sc);
        cudaGetSymbolAddress((void**)&S.bd,   g_bd);
        cudaGetSymbolAddress((void**)&S.attn, g_attn);
        cudaGetSymbolAddress((void**)&S.ao,   g_ao);
        cudaGetSymbolAddress((void**)&S.y,    g_y);
        cudaGetSymbolAddress((void**)&S.mid,  g_mid);
        S.init = true;
    }

    detect_seg_kernel<<<1, 32>>>((const unsigned char*)seg);

    const float* x = content;
    const int rowsQ = B_ * QLEN_;   // 1024
    const int rowsC = B_ * CLEN_;   // 2048
    const int rowsR = B_ * RLEN_;   // 3072

    for (int l = 0; l < L_; l++) {
        long long wofs = (long long)l * H_ * H_;

        // context = concat(mems[l], x)
        {
            int total = B_ * CLEN_ * H_;
            build_ctx_kernel<<<(total + 255) / 256, 256>>>(
                mems + (long long)l * B_ * MLEN_ * H_, x);
        }

        // projections
        launch_gemm(false, x,      w_q + wofs, S.q, rowsQ, H_, H_, H_, H_, H_,
                    nullptr, 0, 1, 1, 0,0,0,0,0,0);
        launch_gemm(false, S.ctx,  w_k + wofs, S.k, rowsC, H_, H_, H_, H_, H_,
                    nullptr, 0, 1, 1, 0,0,0,0,0,0);
        launch_gemm(false, S.ctx,  w_v + wofs, S.v, rowsC, H_, H_, H_, H_, H_,
                    nullptr, 0, 1, 1, 0,0,0,0,0,0);
        launch_gemm(false, posenc, w_r + wofs, S.r, rowsR, H_, H_, H_, H_, H_,
                    nullptr, 0, 1, 1, 0,0,0,0,0,0);

        // q + biases; segment dots
        {
            int total = B_ * QLEN_ * H_;
            make_qcp_kernel<<<(total + 255) / 256, 256>>>(cbias, pbias);
        }
        ef_kernel<<<B_ * QLEN_, 512>>>(sbias, segenc + (long long)l * 2 * NH_ * D_);

        // ac[b,n]: (512x64) x (1024x64)^T  -> scores buffer
        launch_gemm(true, S.qc, S.k, S.sc,
                    QLEN_, CLEN_, D_, H_, H_, CLEN_,
                    nullptr, 0,
                    B_ * NH_, NH_,
                    (long long)QLEN_ * H_, D_,
                    (long long)CLEN_ * H_, D_,
                    (long long)NH_ * QLEN_ * CLEN_, (long long)QLEN_ * CLEN_);

        // bd[b,n]: (512x64) x (1536x64)^T -> bd buffer
        launch_gemm(true, S.qp, S.r, S.bd,
                    QLEN_, RLEN_, D_, H_, H_, RLEN_,
                    nullptr, 0,
                    B_ * NH_, NH_,
                    (long long)QLEN_ * H_, D_,
                    (long long)RLEN_ * H_, D_,
                    (long long)NH_ * QLEN_ * RLEN_, (long long)QLEN_ * RLEN_);

        // fused scores + rel-shift + segment + mask + softmax (in place -> probs)
        score_softmax_kernel<<<B_ * NH_ * QLEN_, 256>>>(mask, seg);

        // attn[b,n] = probs (512x1024) x V (1024x64)
        launch_gemm(false, S.sc, S.v, S.attn,
                    QLEN_, D_, CLEN_, CLEN_, H_, H_,
                    nullptr, 0,
                    B_ * NH_, NH_,
                    (long long)NH_ * QLEN_ * CLEN_, (long long)QLEN_ * CLEN_,
                    (long long)CLEN_ * H_, D_,
                    (long long)QLEN_ * H_, D_);

        // attn_out = attn [1024 x 1024] * w_o^T
        launch_gemm(true, S.attn, w_o + wofs, S.ao,
                    rowsQ, H_, H_, H_, H_, H_,
                    nullptr, 0, 1, 1, 0,0,0,0,0,0);

        // y = LN1(attn_out + x)
        ln_kernel<<<rowsQ, 256>>>(S.ao, x, ln1_g + l * H_, ln1_b + l * H_, S.y);

        // FFN (mid = relu(y*W1+b1); ao reused = mid*W2+b2)
        launch_gemm(false, S.y,   ffn_w1 + (long long)l * H_ * F_, S.mid,
                    rowsQ, F_, H_, H_, F_, F_,
                    ffn_b1 + (long long)l * F_, 1, 1, 1, 0,0,0,0,0,0);
        launch_gemm(false, S.mid, ffn_w2 + (long long)l * F_ * H_, S.ao,
                    rowsQ, H_, F_, F_, H_, H_,
                    ffn_b2 + (long long)l * H_, 0, 1, 1, 0,0,0,0,0,0);

        // x_next = LN2(ffn + y)
        float* xout = (l == L_ - 1) ? (float*)d_out : S.x;
        ln_kernel<<<rowsQ, 256>>>(S.ao, S.y, ln2_g + l * H_, ln2_b + l * H_, xout);

        x = S.x;
    }
}

// round 7
// speedup vs baseline: 1.2993x; 1.0252x over previous
#include <cuda_runtime.h>
#include <cuda_bf16.h>
#include <math.h>

// ---------------- problem constants ----------------
#define L_    4
#define B_    2
#define QLEN_ 512
#define MLEN_ 512
#define CLEN_ 1024
#define RLEN_ 1536
#define H_    1024
#define NH_   16
#define D_    64
#define F_    4096
#define LN_EPS_ 1e-12f

#define EFSTRIDE ((long long)B_*NH_*QLEN_)

// ---------------- scratch (device globals; no allocations allowed) ----------------
__device__ float g_x   [B_*QLEN_*H_];
__device__ float g_ctx [B_*CLEN_*H_];
__device__ float g_q   [B_*QLEN_*H_];
__device__ float g_qc  [B_*QLEN_*H_];
__device__ float g_qp  [B_*QLEN_*H_];
__device__ float g_k   [B_*CLEN_*H_];
__device__ float g_v   [B_*CLEN_*H_];
__device__ float g_r   [B_*RLEN_*H_];
__device__ float g_sc  [(long long)B_*NH_*QLEN_*CLEN_];   // scores -> probs (in place)
__device__ float g_bd  [(long long)B_*NH_*QLEN_*RLEN_];
__device__ float g_ef  [2*B_*NH_*QLEN_];
__device__ float g_attn[B_*QLEN_*H_];
__device__ float g_ao  [B_*QLEN_*H_];       // also reused for FFN output
__device__ float g_y   [B_*QLEN_*H_];
__device__ float g_mid [B_*QLEN_*F_];
__device__ int   g_segmode;   // 0=float32, 1=int32, 2=uint8

// ---------------- packed f32x2 helpers (Blackwell) ----------------
#define FMA_F32X2(d, a, b, c) \
    asm("fma.rn.f32x2 %0, %1, %2, %3;" : "=l"(d) : "l"(a), "l"(b), "l"(c))
#define PACK_DUP_F32(out, f) \
    asm("mov.b64 %0, {%1, %1};" : "=l"(out) : "r"(__float_as_uint(f)))
#define UNPACK_F32X2_(lo, hi, in) \
    asm("mov.b64 {%0, %1}, %2;" : "=r"(lo), "=r"(hi) : "l"(in))

// ---------------- high-intensity tiled GEMM (FFMA2 inner loop) ----------------
// C[M,N] = A[M,K] * B  (TB=0: B is [K,N]; TB=1: B is [N,K] -> C=A*B^T)
// 128x128 tile, BK=8, 256 threads, 8x8 per thread (as 8x4 f32x2 pairs),
// float4 smem, double buffer. Requires K%8==0, ld*%4==0 (true here).
#define TM 128
#define TN 128
#define TK 8
#define SPAD 132   // row stride in floats (128 + 4 pad), keeps 16B alignment

template<int TB>
__global__ void __launch_bounds__(256)
gemm_k(const float* __restrict__ A, const float* __restrict__ Bm, float* __restrict__ C,
       int M, int N, int K, int lda, int ldb, int ldc,
       const float* __restrict__ bias, int relu,
       int inner,
       long long oAo, long long oAi, long long oBo, long long oBi,
       long long oCo, long long oCi)
{
    int z  = blockIdx.z;
    int zo = z / inner;
    int zi = z - zo * inner;
    A  += zo * oAo + zi * oAi;
    Bm += zo * oBo + zi * oBi;
    C  += zo * oCo + zi * oCi;

    __shared__ float As[2][TK][SPAD];
    __shared__ float Bs[2][TK][SPAD];

    const int t  = threadIdx.x;
    const int m0 = blockIdx.y * TM;
    const int n0 = blockIdx.x * TN;

    // A tile loader: thread -> (row am in [0,128), k-quad ak in {0,4})
    const int am = t & 127;
    const int ak = (t >> 7) << 2;
    // B tile loader
    const int bk  = t >> 5;          // TB==0: k row 0..7
    const int bn  = (t & 31) << 2;   // TB==0: n quad
    const int bn2 = t & 127;         // TB==1: n row
    const int bkk = (t >> 7) << 2;   // TB==1: k quad

    // compute-side fragment coords
    const int tx4 = (t & 15) << 2;
    const int ty4 = (t >> 4) << 2;

    // accumulators: 8 rows x 4 packed col-pairs (cols tx4..tx4+3, tx4+64..tx4+67)
    unsigned long long acc[8][4];
#pragma unroll
    for (int u = 0; u < 8; u++)
#pragma unroll
        for (int v = 0; v < 4; v++) acc[u][v] = 0ULL;

    auto loadA = [&](int k0) -> float4 {
        int gm = m0 + am, gk = k0 + ak;
        if (gm < M && gk < K)
            return *reinterpret_cast<const float4*>(A + (long long)gm * lda + gk);
        return make_float4(0.f, 0.f, 0.f, 0.f);
    };
    auto loadB = [&](int k0) -> float4 {
        if (TB == 0) {
            int gk = k0 + bk, gn = n0 + bn;
            if (gk < K && gn < N)
                return *reinterpret_cast<const float4*>(Bm + (long long)gk * ldb + gn);
        } else {
            int gn = n0 + bn2, gk = k0 + bkk;
            if (gn < N && gk < K)
                return *reinterpret_cast<const float4*>(Bm + (long long)gn * ldb + gk);
        }
        return make_float4(0.f, 0.f, 0.f, 0.f);
    };
    auto storeTiles = [&](int buf, float4 a, float4 b) {
        As[buf][ak + 0][am] = a.x;
        As[buf][ak + 1][am] = a.y;
        As[buf][ak + 2][am] = a.z;
        As[buf][ak + 3][am] = a.w;
        if (TB == 0) {
            *reinterpret_cast<float4*>(&Bs[buf][bk][bn]) = b;
        } else {
            Bs[buf][bkk + 0][bn2] = b.x;
            Bs[buf][bkk + 1][bn2] = b.y;
            Bs[buf][bkk + 2][bn2] = b.z;
            Bs[buf][bkk + 3][bn2] = b.w;
        }
    };

    auto compute = [&](int buf) {
#pragma unroll
        for (int k = 0; k < TK; k++) {
            float4 a0 = *reinterpret_cast<const float4*>(&As[buf][k][ty4]);
            float4 a1 = *reinterpret_cast<const float4*>(&As[buf][k][ty4 + 64]);
            // B pairs read directly as packed 64-bit (consecutive columns)
            ulonglong2 bl0 = *reinterpret_cast<const ulonglong2*>(&Bs[buf][k][tx4]);
            ulonglong2 bl1 = *reinterpret_cast<const ulonglong2*>(&Bs[buf][k][tx4 + 64]);
            unsigned long long bp[4] = {bl0.x, bl0.y, bl1.x, bl1.y};
            float af[8] = {a0.x, a0.y, a0.z, a0.w, a1.x, a1.y, a1.z, a1.w};
            unsigned long long ap[8];
#pragma unroll
            for (int u = 0; u < 8; u++) PACK_DUP_F32(ap[u], af[u]);
#pragma unroll
            for (int u = 0; u < 8; u++)
#pragma unroll
                for (int v = 0; v < 4; v++)
                    FMA_F32X2(acc[u][v], ap[u], bp[v], acc[u][v]);
        }
    };

    // prologue
    {
        float4 a = loadA(0), b = loadB(0);
        storeTiles(0, a, b);
    }
    __syncthreads();

    int buf = 0;
    for (int k0 = TK; k0 < K; k0 += TK) {
        float4 aP = loadA(k0);
        float4 bP = loadB(k0);
        compute(buf);
        storeTiles(buf ^ 1, aP, bP);
        __syncthreads();
        buf ^= 1;
    }
    compute(buf);

    // epilogue
#pragma unroll
    for (int u = 0; u < 8; u++) {
        int gm = m0 + ((u < 4) ? (ty4 + u) : (ty4 + 64 + u - 4));
        if (gm >= M) continue;
        float* crow = C + (long long)gm * ldc;
#pragma unroll
        for (int v = 0; v < 4; v++) {
            int gn = n0 + ((v < 2) ? (tx4 + 2 * v) : (tx4 + 64 + 2 * (v - 2)));
            unsigned int lo, hi;
            UNPACK_F32X2_(lo, hi, acc[u][v]);
            float vlo = __uint_as_float(lo);
            float vhi = __uint_as_float(hi);
            if (gn < N) {
                float val = vlo;
                if (bias) val += bias[gn];
                if (relu) val = fmaxf(val, 0.f);
                crow[gn] = val;
            }
            if (gn + 1 < N) {
                float val = vhi;
                if (bias) val += bias[gn + 1];
                if (relu) val = fmaxf(val, 0.f);
                crow[gn + 1] = val;
            }
        }
    }
}

static void launch_gemm(bool transB,
                        const float* A, const float* Bm, float* C,
                        int M, int N, int K, int lda, int ldb, int ldc,
                        const float* bias, int relu,
                        int batches, int inner,
                        long long oAo, long long oAi,
                        long long oBo, long long oBi,
                        long long oCo, long long oCi)
{
    dim3 grid((N + TN - 1) / TN, (M + TM - 1) / TM, batches);
    if (transB)
        gemm_k<1><<<grid, 256>>>(A, Bm, C, M, N, K, lda, ldb, ldc, bias, relu,
                                 inner, oAo, oAi, oBo, oBi, oCo, oCi);
    else
        gemm_k<0><<<grid, 256>>>(A, Bm, C, M, N, K, lda, ldb, ldc, bias, relu,
                                 inner, oAo, oAi, oBo, oBi, oCo, oCi);
}

// ---------------- small kernels ----------------

// detect segment_matrix storage dtype by byte pattern of first 1024 bytes
__global__ void detect_seg_kernel(const unsigned char* __restrict__ p)
{
    if (threadIdx.x == 0 && blockIdx.x == 0) {
        bool f32 = false, nonalign = false;
        for (int i = 0; i < 1024; i++) {
            unsigned char c = p[i];
            if ((i & 3) == 3 && c == 0x3F) f32 = true;       // 1.0f high byte
            if ((i & 3) != 0 && c == 1)    nonalign = true;  // packed uint8 ones
        }
        g_segmode = f32 ? 0 : (nonalign ? 2 : 1);
    }
}

// ctx[b, j, h] = j < MLEN ? mems_l[b,j,h] : x[b, j-MLEN, h]
__global__ void build_ctx_kernel(const float* __restrict__ mems_l,
                                 const float* __restrict__ x)
{
    int idx = blockIdx.x * blockDim.x + threadIdx.x;
    if (idx >= B_ * CLEN_ * H_) return;
    int h = idx % H_;
    int j = (idx / H_) % CLEN_;
    int b = idx / (H_ * CLEN_);
    float v = (j < MLEN_) ? mems_l[((long long)b * MLEN_ + j) * H_ + h]
                          : x[((long long)b * QLEN_ + (j - MLEN_)) * H_ + h];
    g_ctx[idx] = v;
}

// qc = q + content_bias, qp = q + position_bias (bias indexed by nd = idx % H)
__global__ void make_qcp_kernel(const float* __restrict__ cb,
                                const float* __restrict__ pb)
{
    int idx = blockIdx.x * blockDim.x + threadIdx.x;
    if (idx >= B_ * QLEN_ * H_) return;
    int nd  = idx % H_;
    float q = g_q[idx];
    g_qc[idx] = q + cb[nd];
    g_qp[idx] = q + pb[nd];
}

// ef[s][b,n,i] = sum_d (q[b,i,n,d] + sb[n,d]) * se_l[s,n,d]
__global__ void ef_kernel(const float* __restrict__ sb,
                          const float* __restrict__ se_l)
{
    int bi   = blockIdx.x;             // b*QLEN + i
    int n    = threadIdx.x >> 5;       // head (16 warps)
    int lane = threadIdx.x & 31;
    const float* qrow = g_q + (long long)bi * H_ + n * D_;
    float s0 = 0.f, s1 = 0.f;
#pragma unroll
    for (int d = lane; d < D_; d += 32) {
        float qv = qrow[d] + sb[n * D_ + d];
        s0 += qv * se_l[n * D_ + d];
        s1 += qv * se_l[NH_ * D_ + n * D_ + d];
    }
#pragma unroll
    for (int o = 16; o > 0; o >>= 1) {
        s0 += __shfl_down_sync(0xFFFFFFFFu, s0, o);
        s1 += __shfl_down_sync(0xFFFFFFFFu, s1, o);
    }
    if (lane == 0) {
        int b = bi / QLEN_;
        int i = bi - b * QLEN_;
        long long ridx = ((long long)(b * NH_ + n) * QLEN_ + i);
        g_ef[ridx]            = s0;
        g_ef[EFSTRIDE + ridx] = s1;
    }
}

// fused: scores = (ac + bd_shifted + ef)/8 + mask*(-1e30); softmax over j; probs in-place
__global__ void __launch_bounds__(256)
score_softmax_kernel(const float* __restrict__ mask, const void* __restrict__ seg)
{
    int row = blockIdx.x;               // over B*NH*QLEN
    int i   = row % QLEN_;
    int bn  = row / QLEN_;
    int b   = bn / NH_;
    int tid = threadIdx.x;

    float*       ac   = g_sc + (long long)bn * QLEN_ * CLEN_ + (long long)i * CLEN_;
    const float* bd   = g_bd + (long long)bn * QLEN_ * RLEN_ + (long long)i * RLEN_ + (QLEN_ - i);
    const float* mrow = mask + ((long long)b * QLEN_ + i) * CLEN_;
    long long    sbase = ((long long)b * QLEN_ + i) * (long long)CLEN_;
    float ef0 = g_ef[(long long)bn * QLEN_ + i];
    float ef1 = g_ef[EFSTRIDE + (long long)bn * QLEN_ + i];
    int mode = g_segmode;
    const float rs = 0.125f;

    float vals[4];
    float lmax = -3.0e38f;
#pragma unroll
    for (int u = 0; u < 4; u++) {
        int j = u * 256 + tid;
        bool s;
        if (mode == 2)      s = ((const unsigned char*)seg)[sbase + j] != 0;
        else if (mode == 1) s = ((const int*)seg)[sbase + j] != 0;
        else                s = ((const float*)seg)[sbase + j] != 0.f;
        float ef = s ? ef1 : ef0;
        float sc = (ac[j] + bd[j] + ef) * rs + mrow[j] * (-1e30f);
        vals[u] = sc;
        lmax = fmaxf(lmax, sc);
    }

    __shared__ float red[256];
    red[tid] = lmax;
    __syncthreads();
    for (int o = 128; o > 0; o >>= 1) {
        if (tid < o) red[tid] = fmaxf(red[tid], red[tid + o]);
        __syncthreads();
    }
    float m = red[0];
    __syncthreads();

    float lsum = 0.f;
#pragma unroll
    for (int u = 0; u < 4; u++) {
        vals[u] = __expf(vals[u] - m);
        lsum += vals[u];
    }
    red[tid] = lsum;
    __syncthreads();
    for (int o = 128; o > 0; o >>= 1) {
        if (tid < o) red[tid] += red[tid + o];
        __syncthreads();
    }
    float inv = 1.f / red[0];
#pragma unroll
    for (int u = 0; u < 4; u++) {
        int j = u * 256 + tid;
        ac[j] = vals[u] * inv;
    }
}

// out = LN(a + b) * gamma + beta   (row = one token, H=1024)
__global__ void __launch_bounds__(256)
ln_kernel(const float* __restrict__ a, const float* __restrict__ b,
          const float* __restrict__ gamma, const float* __restrict__ beta,
          float* __restrict__ out)
{
    int row = blockIdx.x;
    int tid = threadIdx.x;
    const float* pa = a + (long long)row * H_;
    const float* pb = b + (long long)row * H_;

    float v[4];
    float lsum = 0.f;
#pragma unroll
    for (int u = 0; u < 4; u++) {
        int j = u * 256 + tid;
        v[u] = pa[j] + pb[j];
        lsum += v[u];
    }
    __shared__ float red[256];
    red[tid] = lsum;
    __syncthreads();
    for (int o = 128; o > 0; o >>= 1) {
        if (tid < o) red[tid] += red[tid + o];
        __syncthreads();
    }
    float mu = red[0] * (1.0f / H_);
    __syncthreads();

    float lvar = 0.f;
#pragma unroll
    for (int u = 0; u < 4; u++) {
        float d = v[u] - mu;
        lvar += d * d;
    }
    red[tid] = lvar;
    __syncthreads();
    for (int o = 128; o > 0; o >>= 1) {
        if (tid < o) red[tid] += red[tid + o];
        __syncthreads();
    }
    float rstd = rsqrtf(red[0] * (1.0f / H_) + LN_EPS_);
    float* po = out + (long long)row * H_;
#pragma unroll
    for (int u = 0; u < 4; u++) {
        int j = u * 256 + tid;
        po[j] = (v[u] - mu) * rstd * gamma[j] + beta[j];
    }
}

// ---------------- host orchestration ----------------
struct ScratchPtrs {
    float *x, *ctx, *q, *qc, *qp, *k, *v, *r, *sc, *bd, *attn, *ao, *y, *mid;
    bool init = false;
};

extern "C" void kernel_launch(void* const* d_in, const int* in_sizes, int n_in,
                              void* d_out, int out_size)
{
    (void)in_sizes; (void)n_in; (void)out_size;

    const float* content   = (const float*)d_in[0];
    const float* mask      = (const float*)d_in[1];
    const float* posenc    = (const float*)d_in[2];
    const void*  seg       = d_in[3];
    const float* mems      = (const float*)d_in[4];
    const float* w_q       = (const float*)d_in[5];
    const float* w_k       = (const float*)d_in[6];
    const float* w_v       = (const float*)d_in[7];
    const float* w_r       = (const float*)d_in[8];
    const float* w_o       = (const float*)d_in[9];
    const float* ffn_w1    = (const float*)d_in[10];
    const float* ffn_b1    = (const float*)d_in[11];
    const float* ffn_w2    = (const float*)d_in[12];
    const float* ffn_b2    = (const float*)d_in[13];
    const float* ln1_g     = (const float*)d_in[14];
    const float* ln1_b     = (const float*)d_in[15];
    const float* ln2_g     = (const float*)d_in[16];
    const float* ln2_b     = (const float*)d_in[17];
    const float* cbias     = (const float*)d_in[18];
    const float* pbias     = (const float*)d_in[19];
    const float* sbias     = (const float*)d_in[20];
    const float* segenc    = (const float*)d_in[21];

    static ScratchPtrs S;
    if (!S.init) {
        cudaGetSymbolAddress((void**)&S.x,    g_x);
        cudaGetSymbolAddress((void**)&S.ctx,  g_ctx);
        cudaGetSymbolAddress((void**)&S.q,    g_q);
        cudaGetSymbolAddress((void**)&S.qc,   g_qc);
        cudaGetSymbolAddress((void**)&S.qp,   g_qp);
        cudaGetSymbolAddress((void**)&S.k,    g_k);
        cudaGetSymbolAddress((void**)&S.v,    g_v);
        cudaGetSymbolAddress((void**)&S.r,    g_r);
        cudaGetSymbolAddress((void**)&S.sc,   g_sc);
        cudaGetSymbolAddress((void**)&S.bd,   g_bd);
        cudaGetSymbolAddress((void**)&S.attn, g_attn);
        cudaGetSymbolAddress((void**)&S.ao,   g_ao);
        cudaGetSymbolAddress((void**)&S.y,    g_y);
        cudaGetSymbolAddress((void**)&S.mid,  g_mid);
        S.init = true;
    }

    detect_seg_kernel<<<1, 32>>>((const unsigned char*)seg);

    const float* x = content;
    const int rowsQ = B_ * QLEN_;   // 1024
    const int rowsC = B_ * CLEN_;   // 2048
    const int rowsR = B_ * RLEN_;   // 3072

    for (int l = 0; l < L_; l++) {
        long long wofs = (long long)l * H_ * H_;

        // context = concat(mems[l], x)
        {
            int total = B_ * CLEN_ * H_;
            build_ctx_kernel<<<(total + 255) / 256, 256>>>(
                mems + (long long)l * B_ * MLEN_ * H_, x);
        }

        // projections
        launch_gemm(false, x,      w_q + wofs, S.q, rowsQ, H_, H_, H_, H_, H_,
                    nullptr, 0, 1, 1, 0,0,0,0,0,0);
        launch_gemm(false, S.ctx,  w_k + wofs, S.k, rowsC, H_, H_, H_, H_, H_,
                    nullptr, 0, 1, 1, 0,0,0,0,0,0);
        launch_gemm(false, S.ctx,  w_v + wofs, S.v, rowsC, H_, H_, H_, H_, H_,
                    nullptr, 0, 1, 1, 0,0,0,0,0,0);
        launch_gemm(false, posenc, w_r + wofs, S.r, rowsR, H_, H_, H_, H_, H_,
                    nullptr, 0, 1, 1, 0,0,0,0,0,0);

        // q + biases; segment dots
        {
            int total = B_ * QLEN_ * H_;
            make_qcp_kernel<<<(total + 255) / 256, 256>>>(cbias, pbias);
        }
        ef_kernel<<<B_ * QLEN_, 512>>>(sbias, segenc + (long long)l * 2 * NH_ * D_);

        // ac[b,n]: (512x64) x (1024x64)^T  -> scores buffer
        launch_gemm(true, S.qc, S.k, S.sc,
                    QLEN_, CLEN_, D_, H_, H_, CLEN_,
                    nullptr, 0,
                    B_ * NH_, NH_,
                    (long long)QLEN_ * H_, D_,
                    (long long)CLEN_ * H_, D_,
                    (long long)NH_ * QLEN_ * CLEN_, (long long)QLEN_ * CLEN_);

        // bd[b,n]: (512x64) x (1536x64)^T -> bd buffer
        launch_gemm(true, S.qp, S.r, S.bd,
                    QLEN_, RLEN_, D_, H_, H_, RLEN_,
                    nullptr, 0,
                    B_ * NH_, NH_,
                    (long long)QLEN_ * H_, D_,
                    (long long)RLEN_ * H_, D_,
                    (long long)NH_ * QLEN_ * RLEN_, (long long)QLEN_ * RLEN_);

        // fused scores + rel-shift + segment + mask + softmax (in place -> probs)
        score_softmax_kernel<<<B_ * NH_ * QLEN_, 256>>>(mask, seg);

        // attn[b,n] = probs (512x1024) x V (1024x64)
        launch_gemm(false, S.sc, S.v, S.attn,
                    QLEN_, D_, CLEN_, CLEN_, H_, H_,
                    nullptr, 0,
                    B_ * NH_, NH_,
                    (long long)NH_ * QLEN_ * CLEN_, (long long)QLEN_ * CLEN_,
                    (long long)CLEN_ * H_, D_,
                    (long long)QLEN_ * H_, D_);

        // attn_out = attn [1024 x 1024] * w_o^T
        launch_gemm(true, S.attn, w_o + wofs, S.ao,
                    rowsQ, H_, H_, H_, H_, H_,
                    nullptr, 0, 1, 1, 0,0,0,0,0,0);

        // y = LN1(attn_out + x)
        ln_kernel<<<rowsQ, 256>>>(S.ao, x, ln1_g + l * H_, ln1_b + l * H_, S.y);

        // FFN (mid = relu(y*W1+b1); ao reused = mid*W2+b2)
        launch_gemm(false, S.y,   ffn_w1 + (long long)l * H_ * F_, S.mid,
                    rowsQ, F_, H_, H_, F_, F_,
                    ffn_b1 + (long long)l * F_, 1, 1, 1, 0,0,0,0,0,0);
        launch_gemm(false, S.mid, ffn_w2 + (long long)l * F_ * H_, S.ao,
                    rowsQ, H_, F_, F_, H_, H_,
                    ffn_b2 + (long long)l * H_, 0, 1, 1, 0,0,0,0,0,0);

        // x_next = LN2(ffn + y)
        float* xout = (l == L_ - 1) ? (float*)d_out : S.x;
        ln_kernel<<<rowsQ, 256>>>(S.ao, S.y, ln2_g + l * H_, ln2_b + l * H_, xout);

        x = S.x;
    }
}

// round 8
// speedup vs baseline: 2.5057x; 1.9285x over previous
#include <cuda_runtime.h>
#include <cuda_bf16.h>
#include <math.h>

// ---------------- problem constants ----------------
#define L_    4
#define B_    2
#define QLEN_ 512
#define MLEN_ 512
#define CLEN_ 1024
#define RLEN_ 1536
#define H_    1024
#define NH_   16
#define D_    64
#define F_    4096
#define LN_EPS_ 1e-12f

#define EFSTRIDE ((long long)B_*NH_*QLEN_)

// ---------------- scratch (device globals; no allocations allowed) ----------------
__device__ float g_x   [B_*QLEN_*H_];
__device__ float g_ctx [B_*CLEN_*H_];
__device__ float g_q   [B_*QLEN_*H_];
__device__ float g_qc  [B_*QLEN_*H_];
__device__ float g_qp  [B_*QLEN_*H_];
__device__ float g_k   [B_*CLEN_*H_];
__device__ float g_v   [B_*CLEN_*H_];
__device__ float g_r   [B_*RLEN_*H_];
__device__ float g_sc  [(long long)B_*NH_*QLEN_*CLEN_];   // scores -> probs (in place)
__device__ float g_bd  [(long long)B_*NH_*QLEN_*RLEN_];
__device__ float g_ef  [2*B_*NH_*QLEN_];
__device__ float g_attn[B_*QLEN_*H_];
__device__ float g_ao  [B_*QLEN_*H_];       // also reused for FFN output
__device__ float g_y   [B_*QLEN_*H_];
__device__ float g_mid [B_*QLEN_*F_];
__device__ int   g_segmode;   // 0=float32, 1=int32, 2=uint8

// ---------------- tensor-core GEMM (bf16 hi/lo split, fp32-accurate) ----------------
// C[M,N] = A[M,K] * B  (TB=0: B is [K,N]; TB=1: B is [N,K] -> C=A*B^T)
// 128x128 tile, k-chunk 16, 256 threads (8 warps of 64x32), double-buffered smem.
// Each fp32 operand is split a = hi + lo (bf16 each); product via 3 bf16 MMAs:
//   AhBh + AhBl + AlBh  (AlBl ~ 2^-18 relative, negligible). fp32 accumulate.
// Requires M,N multiples of 8 handled by guards; K % 16 == 0 (true: 64/1024/4096),
// lda/ldb % 4 == 0, pointers 16B aligned (true here).
#define TM 128
#define TN 128
#define TKK 16
#define ASTR 24     // halfs per A-style row (16 data + 8 pad) -> 48B, 16B aligned
#define BSTR0 136   // TB=0: halfs per Bs row (128 data + 8 pad) -> 272B, 16B aligned
#define SMTILE 3072 // halfs per operand tile buffer

__device__ __forceinline__ unsigned smaddr(const void* p) {
    return (unsigned)__cvta_generic_to_shared(p);
}
__device__ __forceinline__ unsigned pack2(__nv_bfloat16 a, __nv_bfloat16 b) {
    unsigned short x = __bfloat16_as_ushort(a), y = __bfloat16_as_ushort(b);
    return (unsigned)x | ((unsigned)y << 16);
}
__device__ __forceinline__ void split8(const float* f, unsigned hi[4], unsigned lo[4]) {
#pragma unroll
    for (int j = 0; j < 4; j++) {
        __nv_bfloat16 h0 = __float2bfloat16(f[2*j]);
        __nv_bfloat16 h1 = __float2bfloat16(f[2*j+1]);
        __nv_bfloat16 l0 = __float2bfloat16(f[2*j]   - __bfloat162float(h0));
        __nv_bfloat16 l1 = __float2bfloat16(f[2*j+1] - __bfloat162float(h1));
        hi[j] = pack2(h0, h1);
        lo[j] = pack2(l0, l1);
    }
}

#define LDSM_X4(r, a) asm volatile( \
    "ldmatrix.sync.aligned.m8n8.x4.shared.b16 {%0,%1,%2,%3}, [%4];" \
    : "=r"((r)[0]), "=r"((r)[1]), "=r"((r)[2]), "=r"((r)[3]) : "r"(a))
#define LDSM_X2(r, a) asm volatile( \
    "ldmatrix.sync.aligned.m8n8.x2.shared.b16 {%0,%1}, [%2];" \
    : "=r"((r)[0]), "=r"((r)[1]) : "r"(a))
#define LDSM_X2T(r, a) asm volatile( \
    "ldmatrix.sync.aligned.m8n8.x2.trans.shared.b16 {%0,%1}, [%2];" \
    : "=r"((r)[0]), "=r"((r)[1]) : "r"(a))
#define MMA_BF16(c, a, b) asm volatile( \
    "mma.sync.aligned.m16n8k16.row.col.f32.bf16.bf16.f32 " \
    "{%0,%1,%2,%3}, {%4,%5,%6,%7}, {%8,%9}, {%0,%1,%2,%3};" \
    : "+f"((c)[0]), "+f"((c)[1]), "+f"((c)[2]), "+f"((c)[3]) \
    : "r"((a)[0]), "r"((a)[1]), "r"((a)[2]), "r"((a)[3]), "r"((b)[0]), "r"((b)[1]))

template<int TB>
__global__ void __launch_bounds__(256)
gemm_k(const float* __restrict__ A, const float* __restrict__ Bm, float* __restrict__ C,
       int M, int N, int K, int lda, int ldb, int ldc,
       const float* __restrict__ bias, int relu,
       int inner,
       long long oAo, long long oAi, long long oBo, long long oBi,
       long long oCo, long long oCi)
{
    int z  = blockIdx.z;
    int zo = z / inner;
    int zi = z - zo * inner;
    A  += zo * oAo + zi * oAi;
    Bm += zo * oBo + zi * oBi;
    C  += zo * oCo + zi * oCi;

    // [buf][0=Ahi 1=Alo 2=Bhi 3=Blo][SMTILE halfs]  => 48KB total
    __shared__ __align__(16) __nv_bfloat16 sm[2][4][SMTILE];

    const int t    = threadIdx.x;
    const int lane = t & 31;
    const int warp = t >> 5;
    const int m0 = blockIdx.y * TM;
    const int n0 = blockIdx.x * TN;
    const int wm = (warp & 1) * 64;   // warp tile: 64 rows x 32 cols
    const int wn = (warp >> 1) * 32;

    // loader coords
    const int lrow = t >> 1;          // 0..127 (A rows; TB=1 B rows)
    const int lcol = (t & 1) * 8;     // 0 or 8 (k offset)
    const int bk   = t >> 4;          // 0..15 (TB=0: k row)
    const int bn   = (t & 15) * 8;    // 0..120 (TB=0: n offset)

    float acc[4][4][4];
#pragma unroll
    for (int mf = 0; mf < 4; mf++)
#pragma unroll
        for (int nf = 0; nf < 4; nf++)
#pragma unroll
            for (int e = 0; e < 4; e++) acc[mf][nf][e] = 0.f;

    float4 aR0, aR1, bR0, bR1;
    const float4 Z4 = make_float4(0.f, 0.f, 0.f, 0.f);

    auto loadG = [&](int k0) {
        int gm = m0 + lrow;
        if (gm < M) {
            const float* p = A + (long long)gm * lda + k0 + lcol;
            aR0 = *reinterpret_cast<const float4*>(p);
            aR1 = *reinterpret_cast<const float4*>(p + 4);
        } else { aR0 = Z4; aR1 = Z4; }
        if (TB == 0) {
            int gn = n0 + bn;
            if (gn < N) {
                const float* p = Bm + (long long)(k0 + bk) * ldb + gn;
                bR0 = *reinterpret_cast<const float4*>(p);
                bR1 = *reinterpret_cast<const float4*>(p + 4);
            } else { bR0 = Z4; bR1 = Z4; }
        } else {
            int gn = n0 + lrow;
            if (gn < N) {
                const float* p = Bm + (long long)gn * ldb + k0 + lcol;
                bR0 = *reinterpret_cast<const float4*>(p);
                bR1 = *reinterpret_cast<const float4*>(p + 4);
            } else { bR0 = Z4; bR1 = Z4; }
        }
    };

    auto storeT = [&](int buf) {
        float fa[8] = {aR0.x, aR0.y, aR0.z, aR0.w, aR1.x, aR1.y, aR1.z, aR1.w};
        unsigned hi[4], lo[4];
        split8(fa, hi, lo);
        *reinterpret_cast<uint4*>(&sm[buf][0][lrow * ASTR + lcol]) = make_uint4(hi[0], hi[1], hi[2], hi[3]);
        *reinterpret_cast<uint4*>(&sm[buf][1][lrow * ASTR + lcol]) = make_uint4(lo[0], lo[1], lo[2], lo[3]);
        float fb[8] = {bR0.x, bR0.y, bR0.z, bR0.w, bR1.x, bR1.y, bR1.z, bR1.w};
        split8(fb, hi, lo);
        if (TB == 0) {
            *reinterpret_cast<uint4*>(&sm[buf][2][bk * BSTR0 + bn]) = make_uint4(hi[0], hi[1], hi[2], hi[3]);
            *reinterpret_cast<uint4*>(&sm[buf][3][bk * BSTR0 + bn]) = make_uint4(lo[0], lo[1], lo[2], lo[3]);
        } else {
            *reinterpret_cast<uint4*>(&sm[buf][2][lrow * ASTR + lcol]) = make_uint4(hi[0], hi[1], hi[2], hi[3]);
            *reinterpret_cast<uint4*>(&sm[buf][3][lrow * ASTR + lcol]) = make_uint4(lo[0], lo[1], lo[2], lo[3]);
        }
    };

    auto compute = [&](int buf) {
        // A fragment base: rows wm + (lane&15), k-chunk (lane>>4)*8
        unsigned aHi = smaddr(&sm[buf][0][(wm + (lane & 15)) * ASTR + (lane >> 4) * 8]);
        unsigned aLo = aHi + 2 * SMTILE;   // bytes between operand arrays
        unsigned bHi, bLo;
        if (TB == 0)
            bHi = smaddr(&sm[buf][2][(lane & 15) * BSTR0 + wn]);
        else
            bHi = smaddr(&sm[buf][2][(wn + (lane & 7)) * ASTR + ((lane >> 3) & 1) * 8]);
        bLo = bHi + 2 * SMTILE;

        unsigned ah[4][4], bh[4][2], bl[4][2];
#pragma unroll
        for (int mf = 0; mf < 4; mf++) LDSM_X4(ah[mf], aHi + mf * (16 * ASTR * 2));
#pragma unroll
        for (int nf = 0; nf < 4; nf++) {
            if (TB == 0) {
                LDSM_X2T(bh[nf], bHi + nf * 16);
                LDSM_X2T(bl[nf], bLo + nf * 16);
            } else {
                LDSM_X2(bh[nf], bHi + nf * (8 * ASTR * 2));
                LDSM_X2(bl[nf], bLo + nf * (8 * ASTR * 2));
            }
        }
#pragma unroll
        for (int mf = 0; mf < 4; mf++)
#pragma unroll
            for (int nf = 0; nf < 4; nf++)
                MMA_BF16(acc[mf][nf], ah[mf], bh[nf]);
#pragma unroll
        for (int mf = 0; mf < 4; mf++)
#pragma unroll
            for (int nf = 0; nf < 4; nf++)
                MMA_BF16(acc[mf][nf], ah[mf], bl[nf]);
#pragma unroll
        for (int mf = 0; mf < 4; mf++) LDSM_X4(ah[mf], aLo + mf * (16 * ASTR * 2));
#pragma unroll
        for (int mf = 0; mf < 4; mf++)
#pragma unroll
            for (int nf = 0; nf < 4; nf++)
                MMA_BF16(acc[mf][nf], ah[mf], bh[nf]);
    };

    // prologue
    loadG(0);
    storeT(0);
    __syncthreads();

    int buf = 0;
    for (int k0 = TKK; k0 < K; k0 += TKK) {
        loadG(k0);
        compute(buf);
        storeT(buf ^ 1);
        __syncthreads();
        buf ^= 1;
    }
    compute(buf);

    // epilogue
    const int er = lane >> 2;           // 0..7
    const int ec = (lane & 3) * 2;      // 0,2,4,6
#pragma unroll
    for (int mf = 0; mf < 4; mf++) {
#pragma unroll
        for (int nf = 0; nf < 4; nf++) {
            int gm = m0 + wm + mf * 16 + er;
            int gn = n0 + wn + nf * 8 + ec;
#pragma unroll
            for (int e = 0; e < 4; e++) {
                int rm = gm + (e >> 1) * 8;
                int rn = gn + (e & 1);
                if (rm < M && rn < N) {
                    float val = acc[mf][nf][e];
                    if (bias) val += bias[rn];
                    if (relu) val = fmaxf(val, 0.f);
                    C[(long long)rm * ldc + rn] = val;
                }
            }
        }
    }
}

static void launch_gemm(bool transB,
                        const float* A, const float* Bm, float* C,
                        int M, int N, int K, int lda, int ldb, int ldc,
                        const float* bias, int relu,
                        int batches, int inner,
                        long long oAo, long long oAi,
                        long long oBo, long long oBi,
                        long long oCo, long long oCi)
{
    dim3 grid((N + TN - 1) / TN, (M + TM - 1) / TM, batches);
    if (transB)
        gemm_k<1><<<grid, 256>>>(A, Bm, C, M, N, K, lda, ldb, ldc, bias, relu,
                                 inner, oAo, oAi, oBo, oBi, oCo, oCi);
    else
        gemm_k<0><<<grid, 256>>>(A, Bm, C, M, N, K, lda, ldb, ldc, bias, relu,
                                 inner, oAo, oAi, oBo, oBi, oCo, oCi);
}

// ---------------- small kernels ----------------

// detect segment_matrix storage dtype by byte pattern of first 1024 bytes
__global__ void detect_seg_kernel(const unsigned char* __restrict__ p)
{
    if (threadIdx.x == 0 && blockIdx.x == 0) {
        bool f32 = false, nonalign = false;
        for (int i = 0; i < 1024; i++) {
            unsigned char c = p[i];
            if ((i & 3) == 3 && c == 0x3F) f32 = true;       // 1.0f high byte
            if ((i & 3) != 0 && c == 1)    nonalign = true;  // packed uint8 ones
        }
        g_segmode = f32 ? 0 : (nonalign ? 2 : 1);
    }
}

// ctx[b, j, h] = j < MLEN ? mems_l[b,j,h] : x[b, j-MLEN, h]
__global__ void build_ctx_kernel(const float* __restrict__ mems_l,
                                 const float* __restrict__ x)
{
    int idx = blockIdx.x * blockDim.x + threadIdx.x;
    if (idx >= B_ * CLEN_ * H_) return;
    int h = idx % H_;
    int j = (idx / H_) % CLEN_;
    int b = idx / (H_ * CLEN_);
    float v = (j < MLEN_) ? mems_l[((long long)b * MLEN_ + j) * H_ + h]
                          : x[((long long)b * QLEN_ + (j - MLEN_)) * H_ + h];
    g_ctx[idx] = v;
}

// qc = q + content_bias, qp = q + position_bias (bias indexed by nd = idx % H)
__global__ void make_qcp_kernel(const float* __restrict__ cb,
                                const float* __restrict__ pb)
{
    int idx = blockIdx.x * blockDim.x + threadIdx.x;
    if (idx >= B_ * QLEN_ * H_) return;
    int nd  = idx % H_;
    float q = g_q[idx];
    g_qc[idx] = q + cb[nd];
    g_qp[idx] = q + pb[nd];
}

// ef[s][b,n,i] = sum_d (q[b,i,n,d] + sb[n,d]) * se_l[s,n,d]
__global__ void ef_kernel(const float* __restrict__ sb,
                          const float* __restrict__ se_l)
{
    int bi   = blockIdx.x;             // b*QLEN + i
    int n    = threadIdx.x >> 5;       // head (16 warps)
    int lane = threadIdx.x & 31;
    const float* qrow = g_q + (long long)bi * H_ + n * D_;
    float s0 = 0.f, s1 = 0.f;
#pragma unroll
    for (int d = lane; d < D_; d += 32) {
        float qv = qrow[d] + sb[n * D_ + d];
        s0 += qv * se_l[n * D_ + d];
        s1 += qv * se_l[NH_ * D_ + n * D_ + d];
    }
#pragma unroll
    for (int o = 16; o > 0; o >>= 1) {
        s0 += __shfl_down_sync(0xFFFFFFFFu, s0, o);
        s1 += __shfl_down_sync(0xFFFFFFFFu, s1, o);
    }
    if (lane == 0) {
        int b = bi / QLEN_;
        int i = bi - b * QLEN_;
        long long ridx = ((long long)(b * NH_ + n) * QLEN_ + i);
        g_ef[ridx]            = s0;
        g_ef[EFSTRIDE + ridx] = s1;
    }
}

// fused: scores = (ac + bd_shifted + ef)/8 + mask*(-1e30); softmax over j; probs in-place
__global__ void __launch_bounds__(256)
score_softmax_kernel(const float* __restrict__ mask, const void* __restrict__ seg)
{
    int row = blockIdx.x;               // over B*NH*QLEN
    int i   = row % QLEN_;
    int bn  = row / QLEN_;
    int b   = bn / NH_;
    int tid = threadIdx.x;

    float*       ac   = g_sc + (long long)bn * QLEN_ * CLEN_ + (long long)i * CLEN_;
    const float* bd   = g_bd + (long long)bn * QLEN_ * RLEN_ + (long long)i * RLEN_ + (QLEN_ - i);
    const float* mrow = mask + ((long long)b * QLEN_ + i) * CLEN_;
    long long    sbase = ((long long)b * QLEN_ + i) * (long long)CLEN_;
    float ef0 = g_ef[(long long)bn * QLEN_ + i];
    float ef1 = g_ef[EFSTRIDE + (long long)bn * QLEN_ + i];
    int mode = g_segmode;
    const float rs = 0.125f;

    float vals[4];
    float lmax = -3.0e38f;
#pragma unroll
    for (int u = 0; u < 4; u++) {
        int j = u * 256 + tid;
        bool s;
        if (mode == 2)      s = ((const unsigned char*)seg)[sbase + j] != 0;
        else if (mode == 1) s = ((const int*)seg)[sbase + j] != 0;
        else                s = ((const float*)seg)[sbase + j] != 0.f;
        float ef = s ? ef1 : ef0;
        float sc = (ac[j] + bd[j] + ef) * rs + mrow[j] * (-1e30f);
        vals[u] = sc;
        lmax = fmaxf(lmax, sc);
    }

    __shared__ float red[256];
    red[tid] = lmax;
    __syncthreads();
    for (int o = 128; o > 0; o >>= 1) {
        if (tid < o) red[tid] = fmaxf(red[tid], red[tid + o]);
        __syncthreads();
    }
    float m = red[0];
    __syncthreads();

    float lsum = 0.f;
#pragma unroll
    for (int u = 0; u < 4; u++) {
        vals[u] = __expf(vals[u] - m);
        lsum += vals[u];
    }
    red[tid] = lsum;
    __syncthreads();
    for (int o = 128; o > 0; o >>= 1) {
        if (tid < o) red[tid] += red[tid + o];
        __syncthreads();
    }
    float inv = 1.f / red[0];
#pragma unroll
    for (int u = 0; u < 4; u++) {
        int j = u * 256 + tid;
        ac[j] = vals[u] * inv;
    }
}

// out = LN(a + b) * gamma + beta   (row = one token, H=1024)
__global__ void __launch_bounds__(256)
ln_kernel(const float* __restrict__ a, const float* __restrict__ b,
          const float* __restrict__ gamma, const float* __restrict__ beta,
          float* __restrict__ out)
{
    int row = blockIdx.x;
    int tid = threadIdx.x;
    const float* pa = a + (long long)row * H_;
    const float* pb = b + (long long)row * H_;

    float v[4];
    float lsum = 0.f;
#pragma unroll
    for (int u = 0; u < 4; u++) {
        int j = u * 256 + tid;
        v[u] = pa[j] + pb[j];
        lsum += v[u];
    }
    __shared__ float red[256];
    red[tid] = lsum;
    __syncthreads();
    for (int o = 128; o > 0; o >>= 1) {
        if (tid < o) red[tid] += red[tid + o];
        __syncthreads();
    }
    float mu = red[0] * (1.0f / H_);
    __syncthreads();

    float lvar = 0.f;
#pragma unroll
    for (int u = 0; u < 4; u++) {
        float d = v[u] - mu;
        lvar += d * d;
    }
    red[tid] = lvar;
    __syncthreads();
    for (int o = 128; o > 0; o >>= 1) {
        if (tid < o) red[tid] += red[tid + o];
        __syncthreads();
    }
    float rstd = rsqrtf(red[0] * (1.0f / H_) + LN_EPS_);
    float* po = out + (long long)row * H_;
#pragma unroll
    for (int u = 0; u < 4; u++) {
        int j = u * 256 + tid;
        po[j] = (v[u] - mu) * rstd * gamma[j] + beta[j];
    }
}

// ---------------- host orchestration ----------------
struct ScratchPtrs {
    float *x, *ctx, *q, *qc, *qp, *k, *v, *r, *sc, *bd, *attn, *ao, *y, *mid;
    bool init = false;
};

extern "C" void kernel_launch(void* const* d_in, const int* in_sizes, int n_in,
                              void* d_out, int out_size)
{
    (void)in_sizes; (void)n_in; (void)out_size;

    const float* content   = (const float*)d_in[0];
    const float* mask      = (const float*)d_in[1];
    const float* posenc    = (const float*)d_in[2];
    const void*  seg       = d_in[3];
    const float* mems      = (const float*)d_in[4];
    const float* w_q       = (const float*)d_in[5];
    const float* w_k       = (const float*)d_in[6];
    const float* w_v       = (const float*)d_in[7];
    const float* w_r       = (const float*)d_in[8];
    const float* w_o       = (const float*)d_in[9];
    const float* ffn_w1    = (const float*)d_in[10];
    const float* ffn_b1    = (const float*)d_in[11];
    const float* ffn_w2    = (const float*)d_in[12];
    const float* ffn_b2    = (const float*)d_in[13];
    const float* ln1_g     = (const float*)d_in[14];
    const float* ln1_b     = (const float*)d_in[15];
    const float* ln2_g     = (const float*)d_in[16];
    const float* ln2_b     = (const float*)d_in[17];
    const float* cbias     = (const float*)d_in[18];
    const float* pbias     = (const float*)d_in[19];
    const float* sbias     = (const float*)d_in[20];
    const float* segenc    = (const float*)d_in[21];

    static ScratchPtrs S;
    if (!S.init) {
        cudaGetSymbolAddress((void**)&S.x,    g_x);
        cudaGetSymbolAddress((void**)&S.ctx,  g_ctx);
        cudaGetSymbolAddress((void**)&S.q,    g_q);
        cudaGetSymbolAddress((void**)&S.qc,   g_qc);
        cudaGetSymbolAddress((void**)&S.qp,   g_qp);
        cudaGetSymbolAddress((void**)&S.k,    g_k);
        cudaGetSymbolAddress((void**)&S.v,    g_v);
        cudaGetSymbolAddress((void**)&S.r,    g_r);
        cudaGetSymbolAddress((void**)&S.sc,   g_sc);
        cudaGetSymbolAddress((void**)&S.bd,   g_bd);
        cudaGetSymbolAddress((void**)&S.attn, g_attn);
        cudaGetSymbolAddress((void**)&S.ao,   g_ao);
        cudaGetSymbolAddress((void**)&S.y,    g_y);
        cudaGetSymbolAddress((void**)&S.mid,  g_mid);
        S.init = true;
    }

    detect_seg_kernel<<<1, 32>>>((const unsigned char*)seg);

    const float* x = content;
    const int rowsQ = B_ * QLEN_;   // 1024
    const int rowsC = B_ * CLEN_;   // 2048
    const int rowsR = B_ * RLEN_;   // 3072

    for (int l = 0; l < L_; l++) {
        long long wofs = (long long)l * H_ * H_;

        // context = concat(mems[l], x)
        {
            int total = B_ * CLEN_ * H_;
            build_ctx_kernel<<<(total + 255) / 256, 256>>>(
                mems + (long long)l * B_ * MLEN_ * H_, x);
        }

        // projections
        launch_gemm(false, x,      w_q + wofs, S.q, rowsQ, H_, H_, H_, H_, H_,
                    nullptr, 0, 1, 1, 0,0,0,0,0,0);
        launch_gemm(false, S.ctx,  w_k + wofs, S.k, rowsC, H_, H_, H_, H_, H_,
                    nullptr, 0, 1, 1, 0,0,0,0,0,0);
        launch_gemm(false, S.ctx,  w_v + wofs, S.v, rowsC, H_, H_, H_, H_, H_,
                    nullptr, 0, 1, 1, 0,0,0,0,0,0);
        launch_gemm(false, posenc, w_r + wofs, S.r, rowsR, H_, H_, H_, H_, H_,
                    nullptr, 0, 1, 1, 0,0,0,0,0,0);

        // q + biases; segment dots
        {
            int total = B_ * QLEN_ * H_;
            make_qcp_kernel<<<(total + 255) / 256, 256>>>(cbias, pbias);
        }
        ef_kernel<<<B_ * QLEN_, 512>>>(sbias, segenc + (long long)l * 2 * NH_ * D_);

        // ac[b,n]: (512x64) x (1024x64)^T  -> scores buffer
        launch_gemm(true, S.qc, S.k, S.sc,
                    QLEN_, CLEN_, D_, H_, H_, CLEN_,
                    nullptr, 0,
                    B_ * NH_, NH_,
                    (long long)QLEN_ * H_, D_,
                    (long long)CLEN_ * H_, D_,
                    (long long)NH_ * QLEN_ * CLEN_, (long long)QLEN_ * CLEN_);

        // bd[b,n]: (512x64) x (1536x64)^T -> bd buffer
        launch_gemm(true, S.qp, S.r, S.bd,
                    QLEN_, RLEN_, D_, H_, H_, RLEN_,
                    nullptr, 0,
                    B_ * NH_, NH_,
                    (long long)QLEN_ * H_, D_,
                    (long long)RLEN_ * H_, D_,
                    (long long)NH_ * QLEN_ * RLEN_, (long long)QLEN_ * RLEN_);

        // fused scores + rel-shift + segment + mask + softmax (in place -> probs)
        score_softmax_kernel<<<B_ * NH_ * QLEN_, 256>>>(mask, seg);

        // attn[b,n] = probs (512x1024) x V (1024x64)
        launch_gemm(false, S.sc, S.v, S.attn,
                    QLEN_, D_, CLEN_, CLEN_, H_, H_,
                    nullptr, 0,
                    B_ * NH_, NH_,
                    (long long)NH_ * QLEN_ * CLEN_, (long long)QLEN_ * CLEN_,
                    (long long)CLEN_ * H_, D_,
                    (long long)QLEN_ * H_, D_);

        // attn_out = attn [1024 x 1024] * w_o^T
        launch_gemm(true, S.attn, w_o + wofs, S.ao,
                    rowsQ, H_, H_, H_, H_, H_,
                    nullptr, 0, 1, 1, 0,0,0,0,0,0);

        // y = LN1(attn_out + x)
        ln_kernel<<<rowsQ, 256>>>(S.ao, x, ln1_g + l * H_, ln1_b + l * H_, S.y);

        // FFN (mid = relu(y*W1+b1); ao reused = mid*W2+b2)
        launch_gemm(false, S.y,   ffn_w1 + (long long)l * H_ * F_, S.mid,
                    rowsQ, F_, H_, H_, F_, F_,
                    ffn_b1 + (long long)l * F_, 1, 1, 1, 0,0,0,0,0,0);
        launch_gemm(false, S.mid, ffn_w2 + (long long)l * F_ * H_, S.ao,
                    rowsQ, H_, F_, F_, H_, H_,
                    ffn_b2 + (long long)l * H_, 0, 1, 1, 0,0,0,0,0,0);

        // x_next = LN2(ffn + y)
        float* xout = (l == L_ - 1) ? (float*)d_out : S.x;
        ln_kernel<<<rowsQ, 256>>>(S.ao, S.y, ln2_g + l * H_, ln2_b + l * H_, xout);

        x = S.x;
    }
}

// round 9
// speedup vs baseline: 2.6588x; 1.0611x over previous
#include <cuda_runtime.h>
#include <cuda_bf16.h>
#include <math.h>

// ---------------- problem constants ----------------
#define L_    4
#define B_    2
#define QLEN_ 512
#define MLEN_ 512
#define CLEN_ 1024
#define RLEN_ 1536
#define H_    1024
#define NH_   16
#define D_    64
#define F_    4096
#define LN_EPS_ 1e-12f

#define EFSTRIDE ((long long)B_*NH_*QLEN_)
#define PADE 1024   // tail padding on split arrays (pv reads past N=64 edge)

typedef __nv_bfloat16 bf16;
typedef __nv_bfloat162 bf162;

// ---------------- fp32 scratch ----------------
__device__ float g_x  [B_*QLEN_*H_];
__device__ float g_q  [B_*QLEN_*H_];
__device__ float g_sc [(long long)B_*NH_*QLEN_*CLEN_];
__device__ float g_bd [(long long)B_*NH_*QLEN_*RLEN_];
__device__ float g_ef [2*B_*NH_*QLEN_];
__device__ float g_ao [B_*QLEN_*H_];
__device__ float g_y  [B_*QLEN_*H_];
__device__ int   g_segmode;

// ---------------- bf16 hi/lo split scratch ----------------
__device__ bf16 g_xh [B_*QLEN_*H_+PADE],  g_xl [B_*QLEN_*H_+PADE];
__device__ bf16 g_cth[B_*CLEN_*H_+PADE],  g_ctl[B_*CLEN_*H_+PADE];
__device__ bf16 g_peh[B_*RLEN_*H_+PADE],  g_pel[B_*RLEN_*H_+PADE];
__device__ bf16 g_qch[B_*QLEN_*H_+PADE],  g_qcl[B_*QLEN_*H_+PADE];
__device__ bf16 g_qph[B_*QLEN_*H_+PADE],  g_qpl[B_*QLEN_*H_+PADE];
__device__ bf16 g_kh [B_*CLEN_*H_+PADE],  g_kl [B_*CLEN_*H_+PADE];
__device__ bf16 g_vh [B_*CLEN_*H_+PADE],  g_vl [B_*CLEN_*H_+PADE];
__device__ bf16 g_rh [B_*RLEN_*H_+PADE],  g_rl [B_*RLEN_*H_+PADE];
__device__ bf16 g_ph [(long long)B_*NH_*QLEN_*CLEN_+PADE], g_pl[(long long)B_*NH_*QLEN_*CLEN_+PADE];
__device__ bf16 g_ath[B_*QLEN_*H_+PADE],  g_atl[B_*QLEN_*H_+PADE];
__device__ bf16 g_yh [B_*QLEN_*H_+PADE],  g_yl [B_*QLEN_*H_+PADE];
__device__ bf16 g_mih[B_*QLEN_*F_+PADE],  g_mil[B_*QLEN_*F_+PADE];
// weights
__device__ bf16 g_wqh[L_*H_*H_+PADE], g_wql[L_*H_*H_+PADE];
__device__ bf16 g_wkh[L_*H_*H_+PADE], g_wkl[L_*H_*H_+PADE];
__device__ bf16 g_wvh[L_*H_*H_+PADE], g_wvl[L_*H_*H_+PADE];
__device__ bf16 g_wrh[L_*H_*H_+PADE], g_wrl[L_*H_*H_+PADE];
__device__ bf16 g_woh[L_*H_*H_+PADE], g_wol[L_*H_*H_+PADE];
__device__ bf16 g_f1h[L_*H_*F_+PADE], g_f1l[L_*H_*F_+PADE];
__device__ bf16 g_f2h[L_*F_*H_+PADE], g_f2l[L_*F_*H_+PADE];

__device__ __forceinline__ void split1(float v, bf16& h, bf16& l) {
    h = __float2bfloat16(v);
    l = __float2bfloat16(v - __bfloat162float(h));
}

// ---------------- tensor-core GEMM: pre-split bf16 hi/lo, cp.async 3-stage ----------------
// C[M,N] = A[M,K]*B ; TB=0: B is [K,N]; TB=1: B is [N,K] (C=A*B^T).
// A,B given as (hi,lo) bf16 pairs of the fp32 originals. Product via 3 bf16 MMAs
// (AhBh + AhBl + AlBh), fp32 accumulate. C out: fp32 and/or bf16 hi/lo split.
// 128x128 tile, k-chunk 16, 256 threads (8 warps x (64x32)).
#define TM 128
#define TN 128
#define ASTR 24       // halfs per 16-k row (16 data + 8 pad) = 48B
#define BSTR0 136     // TB=0: halfs per k-row (128 data + 8 pad) = 272B
#define STAGES_ 3
#define A_ST (128*ASTR)    // halfs per A component per stage
#define B_ST0 (16*BSTR0)
#define B_ST1 (128*ASTR)

__device__ __forceinline__ unsigned smaddr(const void* p) {
    return (unsigned)__cvta_generic_to_shared(p);
}

#define CPA16(dst, src) asm volatile( \
    "cp.async.ca.shared.global [%0], [%1], 16;" :: "r"(dst), "l"(src))
#define CP_COMMIT() asm volatile("cp.async.commit_group;")
#define CP_WAIT1()  asm volatile("cp.async.wait_group 1;")

#define LDSM_X4(r, a) asm volatile( \
    "ldmatrix.sync.aligned.m8n8.x4.shared.b16 {%0,%1,%2,%3}, [%4];" \
    : "=r"((r)[0]), "=r"((r)[1]), "=r"((r)[2]), "=r"((r)[3]) : "r"(a))
#define LDSM_X2(r, a) asm volatile( \
    "ldmatrix.sync.aligned.m8n8.x2.shared.b16 {%0,%1}, [%2];" \
    : "=r"((r)[0]), "=r"((r)[1]) : "r"(a))
#define LDSM_X2T(r, a) asm volatile( \
    "ldmatrix.sync.aligned.m8n8.x2.trans.shared.b16 {%0,%1}, [%2];" \
    : "=r"((r)[0]), "=r"((r)[1]) : "r"(a))
#define MMA_BF16(c, a, b) asm volatile( \
    "mma.sync.aligned.m16n8k16.row.col.f32.bf16.bf16.f32 " \
    "{%0,%1,%2,%3}, {%4,%5,%6,%7}, {%8,%9}, {%0,%1,%2,%3};" \
    : "+f"((c)[0]), "+f"((c)[1]), "+f"((c)[2]), "+f"((c)[3]) \
    : "r"((a)[0]), "r"((a)[1]), "r"((a)[2]), "r"((a)[3]), "r"((b)[0]), "r"((b)[1]))

template<int TB>
__global__ void __launch_bounds__(256)
gemm_bf(const bf16* __restrict__ Ah, const bf16* __restrict__ Al,
        const bf16* __restrict__ Bh, const bf16* __restrict__ Bl,
        float* __restrict__ C, bf16* __restrict__ Ch, bf16* __restrict__ Cl,
        int M, int N, int K, int lda, int ldb, int ldc,
        const float* __restrict__ bias, int relu,
        int inner,
        long long oAo, long long oAi, long long oBo, long long oBi,
        long long oCo, long long oCi)
{
    constexpr int BS = (TB == 0) ? B_ST0 : B_ST1;

    int z  = blockIdx.z;
    int zo = z / inner;
    int zi = z - zo * inner;
    Ah += zo * oAo + zi * oAi;
    Al += zo * oAo + zi * oAi;
    Bh += zo * oBo + zi * oBi;
    Bl += zo * oBo + zi * oBi;
    long long cofs = zo * oCo + zi * oCi;
    if (C)  C  += cofs;
    if (Ch) { Ch += cofs; Cl += cofs; }

    extern __shared__ __align__(16) unsigned char dsm_raw[];
    bf16* sAp = reinterpret_cast<bf16*>(dsm_raw);              // [STAGES][2][A_ST]
    bf16* sBp = sAp + STAGES_ * 2 * A_ST;                      // [STAGES][2][BS]

    const int t    = threadIdx.x;
    const int lane = t & 31;
    const int warp = t >> 5;
    const int m0 = blockIdx.y * TM;
    const int n0 = blockIdx.x * TN;
    const int wm = (warp & 1) * 64;
    const int wn = (warp >> 1) * 32;

    float acc[4][4][4];
#pragma unroll
    for (int mf = 0; mf < 4; mf++)
#pragma unroll
        for (int nf = 0; nf < 4; nf++)
#pragma unroll
            for (int e = 0; e < 4; e++) acc[mf][nf][e] = 0.f;

    // loader coords
    const int ar = t >> 1, ac8 = (t & 1) * 8;          // A / TB=1 B: 128 rows x 2 chunks
    const int b0r = t >> 4, b0c = (t & 15) * 8;        // TB=0 B: 16 rows x 16 chunks

    auto issue = [&](int st, int k0) {
        // A hi/lo
        {
            unsigned d = smaddr(sAp + (st * 2 + 0) * A_ST + ar * ASTR + ac8);
            CPA16(d, Ah + (long long)(m0 + ar) * lda + k0 + ac8);
            unsigned dl = d + A_ST * 2;
            CPA16(dl, Al + (long long)(m0 + ar) * lda + k0 + ac8);
        }
        // B hi/lo
        if (TB == 0) {
            unsigned d = smaddr(sBp + (st * 2 + 0) * BS + b0r * BSTR0 + b0c);
            CPA16(d, Bh + (long long)(k0 + b0r) * ldb + n0 + b0c);
            unsigned dl = d + BS * 2;
            CPA16(dl, Bl + (long long)(k0 + b0r) * ldb + n0 + b0c);
        } else {
            unsigned d = smaddr(sBp + (st * 2 + 0) * BS + ar * ASTR + ac8);
            CPA16(d, Bh + (long long)(n0 + ar) * ldb + k0 + ac8);
            unsigned dl = d + BS * 2;
            CPA16(dl, Bl + (long long)(n0 + ar) * ldb + k0 + ac8);
        }
        CP_COMMIT();
    };

    auto compute = [&](int st) {
        bf16* A0 = sAp + (st * 2 + 0) * A_ST;
        bf16* B0 = sBp + (st * 2 + 0) * BS;
        unsigned aHi = smaddr(A0 + (wm + (lane & 15)) * ASTR + (lane >> 4) * 8);
        unsigned aLo = aHi + A_ST * 2;
        unsigned bHi = (TB == 0)
            ? smaddr(B0 + (lane & 15) * BSTR0 + wn)
            : smaddr(B0 + (wn + (lane & 7)) * ASTR + ((lane >> 3) & 1) * 8);
        unsigned bLo = bHi + BS * 2;

        unsigned ah[4][4], bh[4][2], bl[4][2];
#pragma unroll
        for (int mf = 0; mf < 4; mf++) LDSM_X4(ah[mf], aHi + mf * (16 * ASTR * 2));
#pragma unroll
        for (int nf = 0; nf < 4; nf++) {
            if (TB == 0) {
                LDSM_X2T(bh[nf], bHi + nf * 16);
                LDSM_X2T(bl[nf], bLo + nf * 16);
            } else {
                LDSM_X2(bh[nf], bHi + nf * (8 * ASTR * 2));
                LDSM_X2(bl[nf], bLo + nf * (8 * ASTR * 2));
            }
        }
#pragma unroll
        for (int mf = 0; mf < 4; mf++)
#pragma unroll
            for (int nf = 0; nf < 4; nf++)
                MMA_BF16(acc[mf][nf], ah[mf], bh[nf]);
#pragma unroll
        for (int mf = 0; mf < 4; mf++)
#pragma unroll
            for (int nf = 0; nf < 4; nf++)
                MMA_BF16(acc[mf][nf], ah[mf], bl[nf]);
#pragma unroll
        for (int mf = 0; mf < 4; mf++) LDSM_X4(ah[mf], aLo + mf * (16 * ASTR * 2));
#pragma unroll
        for (int mf = 0; mf < 4; mf++)
#pragma unroll
            for (int nf = 0; nf < 4; nf++)
                MMA_BF16(acc[mf][nf], ah[mf], bh[nf]);
    };

    const int kT = K / 16;
    int issued = 0;
    for (; issued < STAGES_ - 1 && issued < kT; issued++) issue(issued, issued * 16);

    for (int i = 0; i < kT; i++) {
        CP_WAIT1();
        __syncthreads();
        compute(i % STAGES_);
        if (issued < kT) { issue(issued % STAGES_, issued * 16); issued++; }
        else             { CP_COMMIT(); }   // keep group accounting aligned
    }

    // epilogue
    const int er = lane >> 2;
    const int ec = (lane & 3) * 2;
#pragma unroll
    for (int mf = 0; mf < 4; mf++) {
#pragma unroll
        for (int nf = 0; nf < 4; nf++) {
            int gm = m0 + wm + mf * 16 + er;
            int gn = n0 + wn + nf * 8 + ec;
#pragma unroll
            for (int half = 0; half < 2; half++) {
                int rm = gm + half * 8;
                if (rm >= M) continue;
                float v0 = acc[mf][nf][half * 2 + 0];
                float v1 = acc[mf][nf][half * 2 + 1];
                if (gn + 1 < N || gn < N) {
                    if (bias) { v0 += bias[gn]; if (gn + 1 < N) v1 += bias[gn + 1]; }
                    if (relu) { v0 = fmaxf(v0, 0.f); v1 = fmaxf(v1, 0.f); }
                    if (gn < N) {
                        if (C) {
                            C[(long long)rm * ldc + gn] = v0;
                            if (gn + 1 < N) C[(long long)rm * ldc + gn + 1] = v1;
                        }
                        if (Ch && gn + 1 < N) {
                            bf16 h0, l0, h1, l1;
                            split1(v0, h0, l0); split1(v1, h1, l1);
                            bf162 hp; hp.x = h0; hp.y = h1;
                            bf162 lp; lp.x = l0; lp.y = l1;
                            *reinterpret_cast<bf162*>(&Ch[(long long)rm * ldc + gn]) = hp;
                            *reinterpret_cast<bf162*>(&Cl[(long long)rm * ldc + gn]) = lp;
                        }
                    }
                }
            }
        }
    }
}

static inline int smem_bytes(bool transB) {
    int bs = transB ? B_ST1 : B_ST0;
    return STAGES_ * 2 * (A_ST + bs) * 2;
}

static void launch_bf(bool transB,
                      const bf16* Ah, const bf16* Al,
                      const bf16* Bh, const bf16* Bl,
                      float* C, bf16* Ch, bf16* Cl,
                      int M, int N, int K, int lda, int ldb, int ldc,
                      const float* bias, int relu,
                      int batches, int inner,
                      long long oAo, long long oAi,
                      long long oBo, long long oBi,
                      long long oCo, long long oCi)
{
    dim3 grid((N + TN - 1) / TN, (M + TM - 1) / TM, batches);
    int sm = smem_bytes(transB);
    if (transB)
        gemm_bf<1><<<grid, 256, sm>>>(Ah, Al, Bh, Bl, C, Ch, Cl, M, N, K, lda, ldb, ldc,
                                      bias, relu, inner, oAo, oAi, oBo, oBi, oCo, oCi);
    else
        gemm_bf<0><<<grid, 256, sm>>>(Ah, Al, Bh, Bl, C, Ch, Cl, M, N, K, lda, ldb, ldc,
                                      bias, relu, inner, oAo, oAi, oBo, oBi, oCo, oCi);
}

// ---------------- split conversion (fp32 -> bf16 hi/lo) ----------------
__global__ void split_kernel(const float4* __restrict__ src,
                             bf162* __restrict__ h, bf162* __restrict__ l, int n4)
{
    int i = blockIdx.x * blockDim.x + threadIdx.x;
    if (i >= n4) return;
    float4 v = src[i];
    bf16 h0, l0, h1, l1, h2, l2, h3, l3;
    split1(v.x, h0, l0); split1(v.y, h1, l1);
    split1(v.z, h2, l2); split1(v.w, h3, l3);
    bf162 a; a.x = h0; a.y = h1;
    bf162 b; b.x = h2; b.y = h3;
    h[2 * i] = a; h[2 * i + 1] = b;
    a.x = l0; a.y = l1; b.x = l2; b.y = l3;
    l[2 * i] = a; l[2 * i + 1] = b;
}
static void launch_split(const float* src, bf16* h, bf16* l, long long n)
{
    int n4 = (int)(n / 4);
    split_kernel<<<(n4 + 255) / 256, 256>>>(
        (const float4*)src, (bf162*)h, (bf162*)l, n4);
}

// ---------------- small kernels ----------------
__global__ void detect_seg_kernel(const unsigned char* __restrict__ p)
{
    if (threadIdx.x == 0 && blockIdx.x == 0) {
        bool f32 = false, nonalign = false;
        for (int i = 0; i < 1024; i++) {
            unsigned char c = p[i];
            if ((i & 3) == 3 && c == 0x3F) f32 = true;
            if ((i & 3) != 0 && c == 1)    nonalign = true;
        }
        g_segmode = f32 ? 0 : (nonalign ? 2 : 1);
    }
}

// ctx split = concat(mems[l], x)
__global__ void build_ctx_kernel(const float* __restrict__ mems_l,
                                 const float* __restrict__ x)
{
    int idx = blockIdx.x * blockDim.x + threadIdx.x;
    if (idx >= B_ * CLEN_ * H_) return;
    int h = idx % H_;
    int j = (idx / H_) % CLEN_;
    int b = idx / (H_ * CLEN_);
    float v = (j < MLEN_) ? mems_l[((long long)b * MLEN_ + j) * H_ + h]
                          : x[((long long)b * QLEN_ + (j - MLEN_)) * H_ + h];
    bf16 hh, ll; split1(v, hh, ll);
    g_cth[idx] = hh; g_ctl[idx] = ll;
}

// qc/qp splits from fp32 q + biases
__global__ void make_qcp_kernel(const float* __restrict__ cb,
                                const float* __restrict__ pb)
{
    int idx = blockIdx.x * blockDim.x + threadIdx.x;
    if (idx >= B_ * QLEN_ * H_) return;
    int nd  = idx % H_;
    float q = g_q[idx];
    bf16 hh, ll;
    split1(q + cb[nd], hh, ll); g_qch[idx] = hh; g_qcl[idx] = ll;
    split1(q + pb[nd], hh, ll); g_qph[idx] = hh; g_qpl[idx] = ll;
}

__global__ void ef_kernel(const float* __restrict__ sb,
                          const float* __restrict__ se_l)
{
    int bi   = blockIdx.x;
    int n    = threadIdx.x >> 5;
    int lane = threadIdx.x & 31;
    const float* qrow = g_q + (long long)bi * H_ + n * D_;
    float s0 = 0.f, s1 = 0.f;
#pragma unroll
    for (int d = lane; d < D_; d += 32) {
        float qv = qrow[d] + sb[n * D_ + d];
        s0 += qv * se_l[n * D_ + d];
        s1 += qv * se_l[NH_ * D_ + n * D_ + d];
    }
#pragma unroll
    for (int o = 16; o > 0; o >>= 1) {
        s0 += __shfl_down_sync(0xFFFFFFFFu, s0, o);
        s1 += __shfl_down_sync(0xFFFFFFFFu, s1, o);
    }
    if (lane == 0) {
        int b = bi / QLEN_;
        int i = bi - b * QLEN_;
        long long ridx = ((long long)(b * NH_ + n) * QLEN_ + i);
        g_ef[ridx]            = s0;
        g_ef[EFSTRIDE + ridx] = s1;
    }
}

// fused scores + rel-shift + segment + mask + softmax -> probs (bf16 split)
__global__ void __launch_bounds__(256)
score_softmax_kernel(const float* __restrict__ mask, const void* __restrict__ seg)
{
    int row = blockIdx.x;
    int i   = row % QLEN_;
    int bn  = row / QLEN_;
    int b   = bn / NH_;
    int tid = threadIdx.x;

    long long rbase = (long long)bn * QLEN_ * CLEN_ + (long long)i * CLEN_;
    const float* ac   = g_sc + rbase;
    const float* bd   = g_bd + (long long)bn * QLEN_ * RLEN_ + (long long)i * RLEN_ + (QLEN_ - i);
    const float* mrow = mask + ((long long)b * QLEN_ + i) * CLEN_;
    long long    sbase = ((long long)b * QLEN_ + i) * (long long)CLEN_;
    float ef0 = g_ef[(long long)bn * QLEN_ + i];
    float ef1 = g_ef[EFSTRIDE + (long long)bn * QLEN_ + i];
    int mode = g_segmode;
    const float rs = 0.125f;

    float vals[4];
    float lmax = -3.0e38f;
#pragma unroll
    for (int u = 0; u < 4; u++) {
        int j = u * 256 + tid;
        bool s;
        if (mode == 2)      s = ((const unsigned char*)seg)[sbase + j] != 0;
        else if (mode == 1) s = ((const int*)seg)[sbase + j] != 0;
        else                s = ((const float*)seg)[sbase + j] != 0.f;
        float ef = s ? ef1 : ef0;
        float sc = (ac[j] + bd[j] + ef) * rs + mrow[j] * (-1e30f);
        vals[u] = sc;
        lmax = fmaxf(lmax, sc);
    }

    __shared__ float red[256];
    red[tid] = lmax;
    __syncthreads();
    for (int o = 128; o > 0; o >>= 1) {
        if (tid < o) red[tid] = fmaxf(red[tid], red[tid + o]);
        __syncthreads();
    }
    float m = red[0];
    __syncthreads();

    float lsum = 0.f;
#pragma unroll
    for (int u = 0; u < 4; u++) {
        vals[u] = __expf(vals[u] - m);
        lsum += vals[u];
    }
    red[tid] = lsum;
    __syncthreads();
    for (int o = 128; o > 0; o >>= 1) {
        if (tid < o) red[tid] += red[tid + o];
        __syncthreads();
    }
    float inv = 1.f / red[0];
#pragma unroll
    for (int u = 0; u < 4; u++) {
        int j = u * 256 + tid;
        bf16 hh, ll; split1(vals[u] * inv, hh, ll);
        g_ph[rbase + j] = hh;
        g_pl[rbase + j] = ll;
    }
}

// out = LN(a + b); fp32 out + optional bf16 split out
__global__ void __launch_bounds__(256)
ln_kernel(const float* __restrict__ a, const float* __restrict__ b,
          const float* __restrict__ gamma, const float* __restrict__ beta,
          float* __restrict__ out, bf16* __restrict__ oh, bf16* __restrict__ ol)
{
    int row = blockIdx.x;
    int tid = threadIdx.x;
    const float* pa = a + (long long)row * H_;
    const float* pb = b + (long long)row * H_;

    float v[4];
    float lsum = 0.f;
#pragma unroll
    for (int u = 0; u < 4; u++) {
        int j = u * 256 + tid;
        v[u] = pa[j] + pb[j];
        lsum += v[u];
    }
    __shared__ float red[256];
    red[tid] = lsum;
    __syncthreads();
    for (int o = 128; o > 0; o >>= 1) {
        if (tid < o) red[tid] += red[tid + o];
        __syncthreads();
    }
    float mu = red[0] * (1.0f / H_);
    __syncthreads();

    float lvar = 0.f;
#pragma unroll
    for (int u = 0; u < 4; u++) {
        float d = v[u] - mu;
        lvar += d * d;
    }
    red[tid] = lvar;
    __syncthreads();
    for (int o = 128; o > 0; o >>= 1) {
        if (tid < o) red[tid] += red[tid + o];
        __syncthreads();
    }
    float rstd = rsqrtf(red[0] * (1.0f / H_) + LN_EPS_);
    float* po = out + (long long)row * H_;
#pragma unroll
    for (int u = 0; u < 4; u++) {
        int j = u * 256 + tid;
        float val = (v[u] - mu) * rstd * gamma[j] + beta[j];
        po[j] = val;
        if (oh) {
            bf16 hh, ll; split1(val, hh, ll);
            oh[(long long)row * H_ + j] = hh;
            ol[(long long)row * H_ + j] = ll;
        }
    }
}

// ---------------- host orchestration ----------------
struct Ptrs {
    float *x, *q, *sc, *bd, *ao, *y;
    bf16 *xh,*xl,*cth,*ctl,*peh,*pel,*qch,*qcl,*qph,*qpl,*kh,*kl,*vh,*vl,*rh,*rl,
         *ph,*pl,*ath,*atl,*yh,*yl,*mih,*mil,
         *wqh,*wql,*wkh,*wkl,*wvh,*wvl,*wrh,*wrl,*woh,*wol,*f1h,*f1l,*f2h,*f2l;
    bool init = false;
};

extern "C" void kernel_launch(void* const* d_in, const int* in_sizes, int n_in,
                              void* d_out, int out_size)
{
    (void)in_sizes; (void)n_in; (void)out_size;

    const float* content   = (const float*)d_in[0];
    const float* mask      = (const float*)d_in[1];
    const float* posenc    = (const float*)d_in[2];
    const void*  seg       = d_in[3];
    const float* mems      = (const float*)d_in[4];
    const float* w_q       = (const float*)d_in[5];
    const float* w_k       = (const float*)d_in[6];
    const float* w_v       = (const float*)d_in[7];
    const float* w_r       = (const float*)d_in[8];
    const float* w_o       = (const float*)d_in[9];
    const float* ffn_w1    = (const float*)d_in[10];
    const float* ffn_b1    = (const float*)d_in[11];
    const float* ffn_w2    = (const float*)d_in[12];
    const float* ffn_b2    = (const float*)d_in[13];
    const float* ln1_g     = (const float*)d_in[14];
    const float* ln1_b     = (const float*)d_in[15];
    const float* ln2_g     = (const float*)d_in[16];
    const float* ln2_b     = (const float*)d_in[17];
    const float* cbias     = (const float*)d_in[18];
    const float* pbias     = (const float*)d_in[19];
    const float* sbias     = (const float*)d_in[20];
    const float* segenc    = (const float*)d_in[21];

    static Ptrs S;
    if (!S.init) {
        cudaGetSymbolAddress((void**)&S.x,  g_x);   cudaGetSymbolAddress((void**)&S.q,  g_q);
        cudaGetSymbolAddress((void**)&S.sc, g_sc);  cudaGetSymbolAddress((void**)&S.bd, g_bd);
        cudaGetSymbolAddress((void**)&S.ao, g_ao);  cudaGetSymbolAddress((void**)&S.y,  g_y);
        cudaGetSymbolAddress((void**)&S.xh, g_xh);  cudaGetSymbolAddress((void**)&S.xl, g_xl);
        cudaGetSymbolAddress((void**)&S.cth,g_cth); cudaGetSymbolAddress((void**)&S.ctl,g_ctl);
        cudaGetSymbolAddress((void**)&S.peh,g_peh); cudaGetSymbolAddress((void**)&S.pel,g_pel);
        cudaGetSymbolAddress((void**)&S.qch,g_qch); cudaGetSymbolAddress((void**)&S.qcl,g_qcl);
        cudaGetSymbolAddress((void**)&S.qph,g_qph); cudaGetSymbolAddress((void**)&S.qpl,g_qpl);
        cudaGetSymbolAddress((void**)&S.kh, g_kh);  cudaGetSymbolAddress((void**)&S.kl, g_kl);
        cudaGetSymbolAddress((void**)&S.vh, g_vh);  cudaGetSymbolAddress((void**)&S.vl, g_vl);
        cudaGetSymbolAddress((void**)&S.rh, g_rh);  cudaGetSymbolAddress((void**)&S.rl, g_rl);
        cudaGetSymbolAddress((void**)&S.ph, g_ph);  cudaGetSymbolAddress((void**)&S.pl, g_pl);
        cudaGetSymbolAddress((void**)&S.ath,g_ath); cudaGetSymbolAddress((void**)&S.atl,g_atl);
        cudaGetSymbolAddress((void**)&S.yh, g_yh);  cudaGetSymbolAddress((void**)&S.yl, g_yl);
        cudaGetSymbolAddress((void**)&S.mih,g_mih); cudaGetSymbolAddress((void**)&S.mil,g_mil);
        cudaGetSymbolAddress((void**)&S.wqh,g_wqh); cudaGetSymbolAddress((void**)&S.wql,g_wql);
        cudaGetSymbolAddress((void**)&S.wkh,g_wkh); cudaGetSymbolAddress((void**)&S.wkl,g_wkl);
        cudaGetSymbolAddress((void**)&S.wvh,g_wvh); cudaGetSymbolAddress((void**)&S.wvl,g_wvl);
        cudaGetSymbolAddress((void**)&S.wrh,g_wrh); cudaGetSymbolAddress((void**)&S.wrl,g_wrl);
        cudaGetSymbolAddress((void**)&S.woh,g_woh); cudaGetSymbolAddress((void**)&S.wol,g_wol);
        cudaGetSymbolAddress((void**)&S.f1h,g_f1h); cudaGetSymbolAddress((void**)&S.f1l,g_f1l);
        cudaGetSymbolAddress((void**)&S.f2h,g_f2h); cudaGetSymbolAddress((void**)&S.f2l,g_f2l);
        cudaFuncSetAttribute((const void*)gemm_bf<0>,
            cudaFuncAttributeMaxDynamicSharedMemorySize, smem_bytes(false));
        cudaFuncSetAttribute((const void*)gemm_bf<1>,
            cudaFuncAttributeMaxDynamicSharedMemorySize, smem_bytes(true));
        S.init = true;
    }

    detect_seg_kernel<<<1, 32>>>((const unsigned char*)seg);

    // one-time (per launch) operand splits
    launch_split(content, S.xh, S.xl, (long long)B_*QLEN_*H_);
    launch_split(posenc,  S.peh, S.pel, (long long)B_*RLEN_*H_);
    launch_split(w_q, S.wqh, S.wql, (long long)L_*H_*H_);
    launch_split(w_k, S.wkh, S.wkl, (long long)L_*H_*H_);
    launch_split(w_v, S.wvh, S.wvl, (long long)L_*H_*H_);
    launch_split(w_r, S.wrh, S.wrl, (long long)L_*H_*H_);
    launch_split(w_o, S.woh, S.wol, (long long)L_*H_*H_);
    launch_split(ffn_w1, S.f1h, S.f1l, (long long)L_*H_*F_);
    launch_split(ffn_w2, S.f2h, S.f2l, (long long)L_*F_*H_);

    const float* x = content;
    const int rowsQ = B_ * QLEN_;   // 1024
    const int rowsC = B_ * CLEN_;   // 2048
    const int rowsR = B_ * RLEN_;   // 3072

    for (int l = 0; l < L_; l++) {
        long long wofs = (long long)l * H_ * H_;

        // ctx split = concat(mems[l], x)
        {
            int total = B_ * CLEN_ * H_;
            build_ctx_kernel<<<(total + 255) / 256, 256>>>(
                mems + (long long)l * B_ * MLEN_ * H_, x);
        }

        // projections
        launch_bf(false, S.xh, S.xl, S.wqh + wofs, S.wql + wofs,
                  S.q, nullptr, nullptr, rowsQ, H_, H_, H_, H_, H_,
                  nullptr, 0, 1, 1, 0,0,0,0,0,0);
        launch_bf(false, S.cth, S.ctl, S.wkh + wofs, S.wkl + wofs,
                  nullptr, S.kh, S.kl, rowsC, H_, H_, H_, H_, H_,
                  nullptr, 0, 1, 1, 0,0,0,0,0,0);
        launch_bf(false, S.cth, S.ctl, S.wvh + wofs, S.wvl + wofs,
                  nullptr, S.vh, S.vl, rowsC, H_, H_, H_, H_, H_,
                  nullptr, 0, 1, 1, 0,0,0,0,0,0);
        launch_bf(false, S.peh, S.pel, S.wrh + wofs, S.wrl + wofs,
                  nullptr, S.rh, S.rl, rowsR, H_, H_, H_, H_, H_,
                  nullptr, 0, 1, 1, 0,0,0,0,0,0);

        // q + biases (splits); segment dots
        {
            int total = B_ * QLEN_ * H_;
            make_qcp_kernel<<<(total + 255) / 256, 256>>>(cbias, pbias);
        }
        ef_kernel<<<B_ * QLEN_, 512>>>(sbias, segenc + (long long)l * 2 * NH_ * D_);

        // ac: (512x64) x (1024x64)^T per head -> fp32 scores
        launch_bf(true, S.qch, S.qcl, S.kh, S.kl,
                  S.sc, nullptr, nullptr,
                  QLEN_, CLEN_, D_, H_, H_, CLEN_,
                  nullptr, 0, B_ * NH_, NH_,
                  (long long)QLEN_ * H_, D_,
                  (long long)CLEN_ * H_, D_,
                  (long long)NH_ * QLEN_ * CLEN_, (long long)QLEN_ * CLEN_);

        // bd: (512x64) x (1536x64)^T per head -> fp32
        launch_bf(true, S.qph, S.qpl, S.rh, S.rl,
                  S.bd, nullptr, nullptr,
                  QLEN_, RLEN_, D_, H_, H_, RLEN_,
                  nullptr, 0, B_ * NH_, NH_,
                  (long long)QLEN_ * H_, D_,
                  (long long)RLEN_ * H_, D_,
                  (long long)NH_ * QLEN_ * RLEN_, (long long)QLEN_ * RLEN_);

        // softmax -> probs split
        score_softmax_kernel<<<B_ * NH_ * QLEN_, 256>>>(mask, seg);

        // pv: probs (512x1024) x V (1024x64) -> attn split
        launch_bf(false, S.ph, S.pl, S.vh, S.vl,
                  nullptr, S.ath, S.atl,
                  QLEN_, D_, CLEN_, CLEN_, H_, H_,
                  nullptr, 0, B_ * NH_, NH_,
                  (long long)NH_ * QLEN_ * CLEN_, (long long)QLEN_ * CLEN_,
                  (long long)CLEN_ * H_, D_,
                  (long long)QLEN_ * H_, D_);

        // out proj: attn x w_o^T -> fp32
        launch_bf(true, S.ath, S.atl, S.woh + wofs, S.wol + wofs,
                  S.ao, nullptr, nullptr, rowsQ, H_, H_, H_, H_, H_,
                  nullptr, 0, 1, 1, 0,0,0,0,0,0);

        // y = LN1(attn_out + x)  (fp32 + split)
        ln_kernel<<<rowsQ, 256>>>(S.ao, x, ln1_g + l * H_, ln1_b + l * H_,
                                  S.y, S.yh, S.yl);

        // FFN
        launch_bf(false, S.yh, S.yl, S.f1h + (long long)l * H_ * F_, S.f1l + (long long)l * H_ * F_,
                  nullptr, S.mih, S.mil, rowsQ, F_, H_, H_, F_, F_,
                  ffn_b1 + (long long)l * F_, 1, 1, 1, 0,0,0,0,0,0);
        launch_bf(false, S.mih, S.mil, S.f2h + (long long)l * F_ * H_, S.f2l + (long long)l * F_ * H_,
                  S.ao, nullptr, nullptr, rowsQ, H_, F_, F_, H_, H_,
                  ffn_b2 + (long long)l * H_, 0, 1, 1, 0,0,0,0,0,0);

        // x_next = LN2(ffn + y)  (fp32 + split for next layer's A)
        float* xout = (l == L_ - 1) ? (float*)d_out : S.x;
        ln_kernel<<<rowsQ, 256>>>(S.ao, S.y, ln2_g + l * H_, ln2_b + l * H_,
                                  xout, S.xh, S.xl);

        x = S.x;
    }
}

// round 10
// speedup vs baseline: 2.7129x; 1.0204x over previous
#include <cuda_runtime.h>
#include <cuda_bf16.h>
#include <math.h>

// ---------------- problem constants ----------------
#define L_    4
#define B_    2
#define QLEN_ 512
#define MLEN_ 512
#define CLEN_ 1024
#define RLEN_ 1536
#define H_    1024
#define NH_   16
#define D_    64
#define F_    4096
#define LN_EPS_ 1e-12f

#define EFSTRIDE ((long long)B_*NH_*QLEN_)
#define PADE 1024

typedef __nv_bfloat16 bf16;
typedef __nv_bfloat162 bf162;

// ---------------- fp32 scratch ----------------
__device__ float g_x  [B_*QLEN_*H_];
__device__ float g_q  [B_*QLEN_*H_];
__device__ float g_sc [(long long)B_*NH_*QLEN_*CLEN_];
__device__ float g_bd [(long long)B_*NH_*QLEN_*RLEN_];
__device__ float g_ef [2*B_*NH_*QLEN_];
__device__ float g_ao [B_*QLEN_*H_];
__device__ float g_y  [B_*QLEN_*H_];
__device__ int   g_segmode;

// ---------------- bf16 hi/lo split scratch ----------------
__device__ bf16 g_xh [B_*QLEN_*H_+PADE],  g_xl [B_*QLEN_*H_+PADE];
__device__ bf16 g_cth[B_*CLEN_*H_+PADE],  g_ctl[B_*CLEN_*H_+PADE];
__device__ bf16 g_peh[B_*RLEN_*H_+PADE],  g_pel[B_*RLEN_*H_+PADE];
__device__ bf16 g_qch[B_*QLEN_*H_+PADE],  g_qcl[B_*QLEN_*H_+PADE];
__device__ bf16 g_qph[B_*QLEN_*H_+PADE],  g_qpl[B_*QLEN_*H_+PADE];
__device__ bf16 g_kh [B_*CLEN_*H_+PADE],  g_kl [B_*CLEN_*H_+PADE];
__device__ bf16 g_vh [B_*CLEN_*H_+PADE],  g_vl [B_*CLEN_*H_+PADE];
__device__ bf16 g_rh [B_*RLEN_*H_+PADE],  g_rl [B_*RLEN_*H_+PADE];
__device__ bf16 g_ph [(long long)B_*NH_*QLEN_*CLEN_+PADE], g_pl[(long long)B_*NH_*QLEN_*CLEN_+PADE];
__device__ bf16 g_ath[B_*QLEN_*H_+PADE],  g_atl[B_*QLEN_*H_+PADE];
__device__ bf16 g_yh [B_*QLEN_*H_+PADE],  g_yl [B_*QLEN_*H_+PADE];
__device__ bf16 g_mih[B_*QLEN_*F_+PADE],  g_mil[B_*QLEN_*F_+PADE];
// weights
__device__ bf16 g_wqh[L_*H_*H_+PADE], g_wql[L_*H_*H_+PADE];
__device__ bf16 g_wkh[L_*H_*H_+PADE], g_wkl[L_*H_*H_+PADE];
__device__ bf16 g_wvh[L_*H_*H_+PADE], g_wvl[L_*H_*H_+PADE];
__device__ bf16 g_wrh[L_*H_*H_+PADE], g_wrl[L_*H_*H_+PADE];
__device__ bf16 g_woh[L_*H_*H_+PADE], g_wol[L_*H_*H_+PADE];
__device__ bf16 g_f1h[L_*H_*F_+PADE], g_f1l[L_*H_*F_+PADE];
__device__ bf16 g_f2h[L_*F_*H_+PADE], g_f2l[L_*F_*H_+PADE];

__device__ __forceinline__ void split1(float v, bf16& h, bf16& l) {
    h = __float2bfloat16(v);
    l = __float2bfloat16(v - __bfloat162float(h));
}

// ---------------- tensor-core GEMM: pre-split bf16 hi/lo, cp.async, 32-deep stages ----
// C[M,N] = A[M,K]*B ; TB=0: B is [K,N]; TB=1: B is [N,K] (C=A*B^T).
// TN_ = 128 (8 warps as 2m x 4n of 64x32) or 64 (2m x 4n of 64x16).
// 3 stages of k=32 each; two 16-k ldmatrix/MMA passes per stage.
// Requires M%128==0, K%32==0 (true for all shapes here).
#define TM 128
#define ASTR32 40           // halfs per 32-k row (32 data + 8 pad) = 80B
#define STAGES_ 3
#define A_ST32 (128*ASTR32) // halfs per A component per stage

__device__ __forceinline__ unsigned smaddr(const void* p) {
    return (unsigned)__cvta_generic_to_shared(p);
}

#define CPA16(dst, src) asm volatile( \
    "cp.async.ca.shared.global [%0], [%1], 16;" :: "r"(dst), "l"(src))
#define CP_COMMIT() asm volatile("cp.async.commit_group;")
#define CP_WAIT1()  asm volatile("cp.async.wait_group 1;")

#define LDSM_X4(r, a) asm volatile( \
    "ldmatrix.sync.aligned.m8n8.x4.shared.b16 {%0,%1,%2,%3}, [%4];" \
    : "=r"((r)[0]), "=r"((r)[1]), "=r"((r)[2]), "=r"((r)[3]) : "r"(a))
#define LDSM_X2(r, a) asm volatile( \
    "ldmatrix.sync.aligned.m8n8.x2.shared.b16 {%0,%1}, [%2];" \
    : "=r"((r)[0]), "=r"((r)[1]) : "r"(a))
#define LDSM_X2T(r, a) asm volatile( \
    "ldmatrix.sync.aligned.m8n8.x2.trans.shared.b16 {%0,%1}, [%2];" \
    : "=r"((r)[0]), "=r"((r)[1]) : "r"(a))
#define MMA_BF16(c, a, b) asm volatile( \
    "mma.sync.aligned.m16n8k16.row.col.f32.bf16.bf16.f32 " \
    "{%0,%1,%2,%3}, {%4,%5,%6,%7}, {%8,%9}, {%0,%1,%2,%3};" \
    : "+f"((c)[0]), "+f"((c)[1]), "+f"((c)[2]), "+f"((c)[3]) \
    : "r"((a)[0]), "r"((a)[1]), "r"((a)[2]), "r"((a)[3]), "r"((b)[0]), "r"((b)[1]))

template<int TB, int TN_>
__global__ void __launch_bounds__(256)
gemm_bf(const bf16* __restrict__ Ah, const bf16* __restrict__ Al,
        const bf16* __restrict__ Bh, const bf16* __restrict__ Bl,
        float* __restrict__ C, bf16* __restrict__ Ch, bf16* __restrict__ Cl,
        int M, int N, int K, int lda, int ldb, int ldc,
        const float* __restrict__ bias, int relu,
        int inner,
        long long oAo, long long oAi, long long oBo, long long oBi,
        long long oCo, long long oCi)
{
    constexpr int NF   = (TN_ == 128) ? 4 : 2;     // n-fragments per warp (8 cols each)
    constexpr int BSTR = TN_ + 8;                  // TB=0 row stride (halfs)
    constexpr int BS   = (TB == 0) ? (32 * BSTR) : A_ST32;  // halfs per B comp per stage

    int z  = blockIdx.z;
    int zo = z / inner;
    int zi = z - zo * inner;
    Ah += zo * oAo + zi * oAi;
    Al += zo * oAo + zi * oAi;
    Bh += zo * oBo + zi * oBi;
    Bl += zo * oBo + zi * oBi;
    long long cofs = zo * oCo + zi * oCi;
    if (C)  C  += cofs;
    if (Ch) { Ch += cofs; Cl += cofs; }

    extern __shared__ __align__(16) unsigned char dsm_raw[];
    bf16* sAp = reinterpret_cast<bf16*>(dsm_raw);          // [STAGES][2][A_ST32]
    bf16* sBp = sAp + STAGES_ * 2 * A_ST32;                // [STAGES][2][BS]

    const int t    = threadIdx.x;
    const int lane = t & 31;
    const int warp = t >> 5;
    const int m0 = blockIdx.y * TM;
    const int n0 = blockIdx.x * TN_;
    const int wm = (warp & 1) * 64;
    const int wn = (warp >> 1) * ((TN_ == 128) ? 32 : 16);

    float acc[4][NF][4];
#pragma unroll
    for (int mf = 0; mf < 4; mf++)
#pragma unroll
        for (int nf = 0; nf < NF; nf++)
#pragma unroll
            for (int e = 0; e < 4; e++) acc[mf][nf][e] = 0.f;

    // loader coords
    const int ar   = t >> 1;            // 0..127 rows (A; TB=1 B)
    const int ak16 = (t & 1) * 16;      // 0 or 16 within 32-k
    const int b0r  = t >> 3;            // 0..31 k-rows (TB=0)
    const int b0c128 = (t & 7) * 16;    // TN=128: 2 chunks
    const int b0c64  = (t & 7) * 8;     // TN=64: 1 chunk

    auto issue = [&](int st, int k0) {
        // A hi/lo: 2+2 cp.async of 16B
        {
            unsigned d = smaddr(sAp + (st * 2) * A_ST32 + ar * ASTR32 + ak16);
            const bf16* s = Ah + (long long)(m0 + ar) * lda + k0 + ak16;
            CPA16(d, s); CPA16(d + 16, s + 8);
            unsigned dl = d + A_ST32 * 2;
            const bf16* sl = Al + (long long)(m0 + ar) * lda + k0 + ak16;
            CPA16(dl, sl); CPA16(dl + 16, sl + 8);
        }
        if (TB == 0) {
            if (TN_ == 128) {
                unsigned d = smaddr(sBp + (st * 2) * BS + b0r * BSTR + b0c128);
                const bf16* s = Bh + (long long)(k0 + b0r) * ldb + n0 + b0c128;
                CPA16(d, s); CPA16(d + 16, s + 8);
                unsigned dl = d + BS * 2;
                const bf16* sl = Bl + (long long)(k0 + b0r) * ldb + n0 + b0c128;
                CPA16(dl, sl); CPA16(dl + 16, sl + 8);
            } else {
                unsigned d = smaddr(sBp + (st * 2) * BS + b0r * BSTR + b0c64);
                CPA16(d, Bh + (long long)(k0 + b0r) * ldb + n0 + b0c64);
                unsigned dl = d + BS * 2;
                CPA16(dl, Bl + (long long)(k0 + b0r) * ldb + n0 + b0c64);
            }
        } else {
            unsigned d = smaddr(sBp + (st * 2) * BS + ar * ASTR32 + ak16);
            const bf16* s = Bh + (long long)(n0 + ar) * ldb + k0 + ak16;
            CPA16(d, s); CPA16(d + 16, s + 8);
            unsigned dl = d + BS * 2;
            const bf16* sl = Bl + (long long)(n0 + ar) * ldb + k0 + ak16;
            CPA16(dl, sl); CPA16(dl + 16, sl + 8);
        }
        CP_COMMIT();
    };

    auto compute = [&](int st) {
        bf16* A0 = sAp + (st * 2) * A_ST32;
        bf16* B0 = sBp + (st * 2) * BS;
#pragma unroll
        for (int p = 0; p < 2; p++) {   // two 16-k passes per 32-k stage
            unsigned aHi = smaddr(A0 + (wm + (lane & 15)) * ASTR32 + p * 16 + (lane >> 4) * 8);
            unsigned aLo = aHi + A_ST32 * 2;
            unsigned bHi = (TB == 0)
                ? smaddr(B0 + (p * 16 + (lane & 15)) * BSTR + wn)
                : smaddr(B0 + (wn + (lane & 7)) * ASTR32 + p * 16 + ((lane >> 3) & 1) * 8);
            unsigned bLo = bHi + BS * 2;

            unsigned ah[4][4], bh[NF][2], bl[NF][2];
#pragma unroll
            for (int mf = 0; mf < 4; mf++) LDSM_X4(ah[mf], aHi + mf * (16 * ASTR32 * 2));
#pragma unroll
            for (int nf = 0; nf < NF; nf++) {
                if (TB == 0) {
                    LDSM_X2T(bh[nf], bHi + nf * 16);
                    LDSM_X2T(bl[nf], bLo + nf * 16);
                } else {
                    LDSM_X2(bh[nf], bHi + nf * (8 * ASTR32 * 2));
                    LDSM_X2(bl[nf], bLo + nf * (8 * ASTR32 * 2));
                }
            }
#pragma unroll
            for (int mf = 0; mf < 4; mf++)
#pragma unroll
                for (int nf = 0; nf < NF; nf++)
                    MMA_BF16(acc[mf][nf], ah[mf], bh[nf]);
#pragma unroll
            for (int mf = 0; mf < 4; mf++)
#pragma unroll
                for (int nf = 0; nf < NF; nf++)
                    MMA_BF16(acc[mf][nf], ah[mf], bl[nf]);
#pragma unroll
            for (int mf = 0; mf < 4; mf++) LDSM_X4(ah[mf], aLo + mf * (16 * ASTR32 * 2));
#pragma unroll
            for (int mf = 0; mf < 4; mf++)
#pragma unroll
                for (int nf = 0; nf < NF; nf++)
                    MMA_BF16(acc[mf][nf], ah[mf], bh[nf]);
        }
    };

    const int kT = K / 32;
    int issued = 0;
    for (; issued < STAGES_ - 1 && issued < kT; issued++) issue(issued, issued * 32);

    for (int i = 0; i < kT; i++) {
        CP_WAIT1();
        __syncthreads();
        compute(i % STAGES_);
        if (issued < kT) { issue(issued % STAGES_, issued * 32); issued++; }
        else             { CP_COMMIT(); }
    }

    // epilogue
    const int er = lane >> 2;
    const int ec = (lane & 3) * 2;
#pragma unroll
    for (int mf = 0; mf < 4; mf++) {
#pragma unroll
        for (int nf = 0; nf < NF; nf++) {
            int gm = m0 + wm + mf * 16 + er;
            int gn = n0 + wn + nf * 8 + ec;
#pragma unroll
            for (int half = 0; half < 2; half++) {
                int rm = gm + half * 8;
                if (rm >= M) continue;
                float v0 = acc[mf][nf][half * 2 + 0];
                float v1 = acc[mf][nf][half * 2 + 1];
                if (bias) { if (gn < N) v0 += bias[gn]; if (gn + 1 < N) v1 += bias[gn + 1]; }
                if (relu) { v0 = fmaxf(v0, 0.f); v1 = fmaxf(v1, 0.f); }
                if (gn < N) {
                    if (C) {
                        C[(long long)rm * ldc + gn] = v0;
                        if (gn + 1 < N) C[(long long)rm * ldc + gn + 1] = v1;
                    }
                    if (Ch && gn + 1 < N) {
                        bf16 h0, l0, h1, l1;
                        split1(v0, h0, l0); split1(v1, h1, l1);
                        bf162 hp; hp.x = h0; hp.y = h1;
                        bf162 lp; lp.x = l0; lp.y = l1;
                        *reinterpret_cast<bf162*>(&Ch[(long long)rm * ldc + gn]) = hp;
                        *reinterpret_cast<bf162*>(&Cl[(long long)rm * ldc + gn]) = lp;
                    }
                }
            }
        }
    }
}

static inline int smem_bytes(int tb, int tn) {
    int bs = (tb == 0) ? 32 * (tn + 8) : A_ST32;
    return STAGES_ * 2 * (A_ST32 + bs) * 2;
}

static void launch_bf(bool transB,
                      const bf16* Ah, const bf16* Al,
                      const bf16* Bh, const bf16* Bl,
                      float* C, bf16* Ch, bf16* Cl,
                      int M, int N, int K, int lda, int ldb, int ldc,
                      const float* bias, int relu,
                      int batches, int inner,
                      long long oAo, long long oAi,
                      long long oBo, long long oBi,
                      long long oCo, long long oCi,
                      bool tn64 = false)
{
    int tn = tn64 ? 64 : 128;
    dim3 grid((N + tn - 1) / tn, (M + TM - 1) / TM, batches);
    int sm = smem_bytes(transB ? 1 : 0, tn);
    if (transB)
        gemm_bf<1,128><<<grid, 256, sm>>>(Ah, Al, Bh, Bl, C, Ch, Cl, M, N, K, lda, ldb, ldc,
                                          bias, relu, inner, oAo, oAi, oBo, oBi, oCo, oCi);
    else if (tn64)
        gemm_bf<0,64><<<grid, 256, sm>>>(Ah, Al, Bh, Bl, C, Ch, Cl, M, N, K, lda, ldb, ldc,
                                         bias, relu, inner, oAo, oAi, oBo, oBi, oCo, oCi);
    else
        gemm_bf<0,128><<<grid, 256, sm>>>(Ah, Al, Bh, Bl, C, Ch, Cl, M, N, K, lda, ldb, ldc,
                                          bias, relu, inner, oAo, oAi, oBo, oBi, oCo, oCi);
}

// ---------------- split conversion (fp32 -> bf16 hi/lo) ----------------
__global__ void split_kernel(const float4* __restrict__ src,
                             bf162* __restrict__ h, bf162* __restrict__ l, int n4)
{
    int i = blockIdx.x * blockDim.x + threadIdx.x;
    if (i >= n4) return;
    float4 v = src[i];
    bf16 h0, l0, h1, l1, h2, l2, h3, l3;
    split1(v.x, h0, l0); split1(v.y, h1, l1);
    split1(v.z, h2, l2); split1(v.w, h3, l3);
    bf162 a; a.x = h0; a.y = h1;
    bf162 b; b.x = h2; b.y = h3;
    h[2 * i] = a; h[2 * i + 1] = b;
    a.x = l0; a.y = l1; b.x = l2; b.y = l3;
    l[2 * i] = a; l[2 * i + 1] = b;
}
static void launch_split(const float* src, bf16* h, bf16* l, long long n)
{
    int n4 = (int)(n / 4);
    split_kernel<<<(n4 + 255) / 256, 256>>>(
        (const float4*)src, (bf162*)h, (bf162*)l, n4);
}

// ---------------- small kernels ----------------
__global__ void detect_seg_kernel(const unsigned char* __restrict__ p)
{
    if (threadIdx.x == 0 && blockIdx.x == 0) {
        bool f32 = false, nonalign = false;
        for (int i = 0; i < 1024; i++) {
            unsigned char c = p[i];
            if ((i & 3) == 3 && c == 0x3F) f32 = true;
            if ((i & 3) != 0 && c == 1)    nonalign = true;
        }
        g_segmode = f32 ? 0 : (nonalign ? 2 : 1);
    }
}

__global__ void build_ctx_kernel(const float* __restrict__ mems_l,
                                 const float* __restrict__ x)
{
    int idx = blockIdx.x * blockDim.x + threadIdx.x;
    if (idx >= B_ * CLEN_ * H_) return;
    int h = idx % H_;
    int j = (idx / H_) % CLEN_;
    int b = idx / (H_ * CLEN_);
    float v = (j < MLEN_) ? mems_l[((long long)b * MLEN_ + j) * H_ + h]
                          : x[((long long)b * QLEN_ + (j - MLEN_)) * H_ + h];
    bf16 hh, ll; split1(v, hh, ll);
    g_cth[idx] = hh; g_ctl[idx] = ll;
}

__global__ void make_qcp_kernel(const float* __restrict__ cb,
                                const float* __restrict__ pb)
{
    int idx = blockIdx.x * blockDim.x + threadIdx.x;
    if (idx >= B_ * QLEN_ * H_) return;
    int nd  = idx % H_;
    float q = g_q[idx];
    bf16 hh, ll;
    split1(q + cb[nd], hh, ll); g_qch[idx] = hh; g_qcl[idx] = ll;
    split1(q + pb[nd], hh, ll); g_qph[idx] = hh; g_qpl[idx] = ll;
}

__global__ void ef_kernel(const float* __restrict__ sb,
                          const float* __restrict__ se_l)
{
    int bi   = blockIdx.x;
    int n    = threadIdx.x >> 5;
    int lane = threadIdx.x & 31;
    const float* qrow = g_q + (long long)bi * H_ + n * D_;
    float s0 = 0.f, s1 = 0.f;
#pragma unroll
    for (int d = lane; d < D_; d += 32) {
        float qv = qrow[d] + sb[n * D_ + d];
        s0 += qv * se_l[n * D_ + d];
        s1 += qv * se_l[NH_ * D_ + n * D_ + d];
    }
#pragma unroll
    for (int o = 16; o > 0; o >>= 1) {
        s0 += __shfl_down_sync(0xFFFFFFFFu, s0, o);
        s1 += __shfl_down_sync(0xFFFFFFFFu, s1, o);
    }
    if (lane == 0) {
        int b = bi / QLEN_;
        int i = bi - b * QLEN_;
        long long ridx = ((long long)(b * NH_ + n) * QLEN_ + i);
        g_ef[ridx]            = s0;
        g_ef[EFSTRIDE + ridx] = s1;
    }
}

__global__ void __launch_bounds__(256)
score_softmax_kernel(const float* __restrict__ mask, const void* __restrict__ seg)
{
    int row = blockIdx.x;
    int i   = row % QLEN_;
    int bn  = row / QLEN_;
    int b   = bn / NH_;
    int tid = threadIdx.x;

    long long rbase = (long long)bn * QLEN_ * CLEN_ + (long long)i * CLEN_;
    const float* ac   = g_sc + rbase;
    const float* bd   = g_bd + (long long)bn * QLEN_ * RLEN_ + (long long)i * RLEN_ + (QLEN_ - i);
    const float* mrow = mask + ((long long)b * QLEN_ + i) * CLEN_;
    long long    sbase = ((long long)b * QLEN_ + i) * (long long)CLEN_;
    float ef0 = g_ef[(long long)bn * QLEN_ + i];
    float ef1 = g_ef[EFSTRIDE + (long long)bn * QLEN_ + i];
    int mode = g_segmode;
    const float rs = 0.125f;

    float vals[4];
    float lmax = -3.0e38f;
#pragma unroll
    for (int u = 0; u < 4; u++) {
        int j = u * 256 + tid;
        bool s;
        if (mode == 2)      s = ((const unsigned char*)seg)[sbase + j] != 0;
        else if (mode == 1) s = ((const int*)seg)[sbase + j] != 0;
        else                s = ((const float*)seg)[sbase + j] != 0.f;
        float ef = s ? ef1 : ef0;
        float sc = (ac[j] + bd[j] + ef) * rs + mrow[j] * (-1e30f);
        vals[u] = sc;
        lmax = fmaxf(lmax, sc);
    }

    __shared__ float red[256];
    red[tid] = lmax;
    __syncthreads();
    for (int o = 128; o > 0; o >>= 1) {
        if (tid < o) red[tid] = fmaxf(red[tid], red[tid + o]);
        __syncthreads();
    }
    float m = red[0];
    __syncthreads();

    float lsum = 0.f;
#pragma unroll
    for (int u = 0; u < 4; u++) {
        vals[u] = __expf(vals[u] - m);
        lsum += vals[u];
    }
    red[tid] = lsum;
    __syncthreads();
    for (int o = 128; o > 0; o >>= 1) {
        if (tid < o) red[tid] += red[tid + o];
        __syncthreads();
    }
    float inv = 1.f / red[0];
#pragma unroll
    for (int u = 0; u < 4; u++) {
        int j = u * 256 + tid;
        bf16 hh, ll; split1(vals[u] * inv, hh, ll);
        g_ph[rbase + j] = hh;
        g_pl[rbase + j] = ll;
    }
}

__global__ void __launch_bounds__(256)
ln_kernel(const float* __restrict__ a, const float* __restrict__ b,
          const float* __restrict__ gamma, const float* __restrict__ beta,
          float* __restrict__ out, bf16* __restrict__ oh, bf16* __restrict__ ol)
{
    int row = blockIdx.x;
    int tid = threadIdx.x;
    const float* pa = a + (long long)row * H_;
    const float* pb = b + (long long)row * H_;

    float v[4];
    float lsum = 0.f;
#pragma unroll
    for (int u = 0; u < 4; u++) {
        int j = u * 256 + tid;
        v[u] = pa[j] + pb[j];
        lsum += v[u];
    }
    __shared__ float red[256];
    red[tid] = lsum;
    __syncthreads();
    for (int o = 128; o > 0; o >>= 1) {
        if (tid < o) red[tid] += red[tid + o];
        __syncthreads();
    }
    float mu = red[0] * (1.0f / H_);
    __syncthreads();

    float lvar = 0.f;
#pragma unroll
    for (int u = 0; u < 4; u++) {
        float d = v[u] - mu;
        lvar += d * d;
    }
    red[tid] = lvar;
    __syncthreads();
    for (int o = 128; o > 0; o >>= 1) {
        if (tid < o) red[tid] += red[tid + o];
        __syncthreads();
    }
    float rstd = rsqrtf(red[0] * (1.0f / H_) + LN_EPS_);
    float* po = out + (long long)row * H_;
#pragma unroll
    for (int u = 0; u < 4; u++) {
        int j = u * 256 + tid;
        float val = (v[u] - mu) * rstd * gamma[j] + beta[j];
        po[j] = val;
        if (oh) {
            bf16 hh, ll; split1(val, hh, ll);
            oh[(long long)row * H_ + j] = hh;
            ol[(long long)row * H_ + j] = ll;
        }
    }
}

// ---------------- host orchestration ----------------
struct Ptrs {
    float *x, *q, *sc, *bd, *ao, *y;
    bf16 *xh,*xl,*cth,*ctl,*peh,*pel,*qch,*qcl,*qph,*qpl,*kh,*kl,*vh,*vl,*rh,*rl,
         *ph,*pl,*ath,*atl,*yh,*yl,*mih,*mil,
         *wqh,*wql,*wkh,*wkl,*wvh,*wvl,*wrh,*wrl,*woh,*wol,*f1h,*f1l,*f2h,*f2l;
    bool init = false;
};

extern "C" void kernel_launch(void* const* d_in, const int* in_sizes, int n_in,
                              void* d_out, int out_size)
{
    (void)in_sizes; (void)n_in; (void)out_size;

    const float* content   = (const float*)d_in[0];
    const float* mask      = (const float*)d_in[1];
    const float* posenc    = (const float*)d_in[2];
    const void*  seg       = d_in[3];
    const float* mems      = (const float*)d_in[4];
    const float* w_q       = (const float*)d_in[5];
    const float* w_k       = (const float*)d_in[6];
    const float* w_v       = (const float*)d_in[7];
    const float* w_r       = (const float*)d_in[8];
    const float* w_o       = (const float*)d_in[9];
    const float* ffn_w1    = (const float*)d_in[10];
    const float* ffn_b1    = (const float*)d_in[11];
    const float* ffn_w2    = (const float*)d_in[12];
    const float* ffn_b2    = (const float*)d_in[13];
    const float* ln1_g     = (const float*)d_in[14];
    const float* ln1_b     = (const float*)d_in[15];
    const float* ln2_g     = (const float*)d_in[16];
    const float* ln2_b     = (const float*)d_in[17];
    const float* cbias     = (const float*)d_in[18];
    const float* pbias     = (const float*)d_in[19];
    const float* sbias     = (const float*)d_in[20];
    const float* segenc    = (const float*)d_in[21];

    static Ptrs S;
    if (!S.init) {
        cudaGetSymbolAddress((void**)&S.x,  g_x);   cudaGetSymbolAddress((void**)&S.q,  g_q);
        cudaGetSymbolAddress((void**)&S.sc, g_sc);  cudaGetSymbolAddress((void**)&S.bd, g_bd);
        cudaGetSymbolAddress((void**)&S.ao, g_ao);  cudaGetSymbolAddress((void**)&S.y,  g_y);
        cudaGetSymbolAddress((void**)&S.xh, g_xh);  cudaGetSymbolAddress((void**)&S.xl, g_xl);
        cudaGetSymbolAddress((void**)&S.cth,g_cth); cudaGetSymbolAddress((void**)&S.ctl,g_ctl);
        cudaGetSymbolAddress((void**)&S.peh,g_peh); cudaGetSymbolAddress((void**)&S.pel,g_pel);
        cudaGetSymbolAddress((void**)&S.qch,g_qch); cudaGetSymbolAddress((void**)&S.qcl,g_qcl);
        cudaGetSymbolAddress((void**)&S.qph,g_qph); cudaGetSymbolAddress((void**)&S.qpl,g_qpl);
        cudaGetSymbolAddress((void**)&S.kh, g_kh);  cudaGetSymbolAddress((void**)&S.kl, g_kl);
        cudaGetSymbolAddress((void**)&S.vh, g_vh);  cudaGetSymbolAddress((void**)&S.vl, g_vl);
        cudaGetSymbolAddress((void**)&S.rh, g_rh);  cudaGetSymbolAddress((void**)&S.rl, g_rl);
        cudaGetSymbolAddress((void**)&S.ph, g_ph);  cudaGetSymbolAddress((void**)&S.pl, g_pl);
        cudaGetSymbolAddress((void**)&S.ath,g_ath); cudaGetSymbolAddress((void**)&S.atl,g_atl);
        cudaGetSymbolAddress((void**)&S.yh, g_yh);  cudaGetSymbolAddress((void**)&S.yl, g_yl);
        cudaGetSymbolAddress((void**)&S.mih,g_mih); cudaGetSymbolAddress((void**)&S.mil,g_mil);
        cudaGetSymbolAddress((void**)&S.wqh,g_wqh); cudaGetSymbolAddress((void**)&S.wql,g_wql);
        cudaGetSymbolAddress((void**)&S.wkh,g_wkh); cudaGetSymbolAddress((void**)&S.wkl,g_wkl);
        cudaGetSymbolAddress((void**)&S.wvh,g_wvh); cudaGetSymbolAddress((void**)&S.wvl,g_wvl);
        cudaGetSymbolAddress((void**)&S.wrh,g_wrh); cudaGetSymbolAddress((void**)&S.wrl,g_wrl);
        cudaGetSymbolAddress((void**)&S.woh,g_woh); cudaGetSymbolAddress((void**)&S.wol,g_wol);
        cudaGetSymbolAddress((void**)&S.f1h,g_f1h); cudaGetSymbolAddress((void**)&S.f1l,g_f1l);
        cudaGetSymbolAddress((void**)&S.f2h,g_f2h); cudaGetSymbolAddress((void**)&S.f2l,g_f2l);
        cudaFuncSetAttribute((const void*)gemm_bf<0,128>,
            cudaFuncAttributeMaxDynamicSharedMemorySize, smem_bytes(0,128));
        cudaFuncSetAttribute((const void*)gemm_bf<1,128>,
            cudaFuncAttributeMaxDynamicSharedMemorySize, smem_bytes(1,128));
        cudaFuncSetAttribute((const void*)gemm_bf<0,64>,
            cudaFuncAttributeMaxDynamicSharedMemorySize, smem_bytes(0,64));
        S.init = true;
    }

    detect_seg_kernel<<<1, 32>>>((const unsigned char*)seg);

    launch_split(content, S.xh, S.xl, (long long)B_*QLEN_*H_);
    launch_split(posenc,  S.peh, S.pel, (long long)B_*RLEN_*H_);
    launch_split(w_q, S.wqh, S.wql, (long long)L_*H_*H_);
    launch_split(w_k, S.wkh, S.wkl, (long long)L_*H_*H_);
    launch_split(w_v, S.wvh, S.wvl, (long long)L_*H_*H_);
    launch_split(w_r, S.wrh, S.wrl, (long long)L_*H_*H_);
    launch_split(w_o, S.woh, S.wol, (long long)L_*H_*H_);
    launch_split(ffn_w1, S.f1h, S.f1l, (long long)L_*H_*F_);
    launch_split(ffn_w2, S.f2h, S.f2l, (long long)L_*F_*H_);

    const float* x = content;
    const int rowsQ = B_ * QLEN_;
    const int rowsC = B_ * CLEN_;
    const int rowsR = B_ * RLEN_;

    for (int l = 0; l < L_; l++) {
        long long wofs = (long long)l * H_ * H_;

        {
            int total = B_ * CLEN_ * H_;
            build_ctx_kernel<<<(total + 255) / 256, 256>>>(
                mems + (long long)l * B_ * MLEN_ * H_, x);
        }

        launch_bf(false, S.xh, S.xl, S.wqh + wofs, S.wql + wofs,
                  S.q, nullptr, nullptr, rowsQ, H_, H_, H_, H_, H_,
                  nullptr, 0, 1, 1, 0,0,0,0,0,0);
        launch_bf(false, S.cth, S.ctl, S.wkh + wofs, S.wkl + wofs,
                  nullptr, S.kh, S.kl, rowsC, H_, H_, H_, H_, H_,
                  nullptr, 0, 1, 1, 0,0,0,0,0,0);
        launch_bf(false, S.cth, S.ctl, S.wvh + wofs, S.wvl + wofs,
                  nullptr, S.vh, S.vl, rowsC, H_, H_, H_, H_, H_,
                  nullptr, 0, 1, 1, 0,0,0,0,0,0);
        launch_bf(false, S.peh, S.pel, S.wrh + wofs, S.wrl + wofs,
                  nullptr, S.rh, S.rl, rowsR, H_, H_, H_, H_, H_,
                  nullptr, 0, 1, 1, 0,0,0,0,0,0);

        {
            int total = B_ * QLEN_ * H_;
            make_qcp_kernel<<<(total + 255) / 256, 256>>>(cbias, pbias);
        }
        ef_kernel<<<B_ * QLEN_, 512>>>(sbias, segenc + (long long)l * 2 * NH_ * D_);

        launch_bf(true, S.qch, S.qcl, S.kh, S.kl,
                  S.sc, nullptr, nullptr,
                  QLEN_, CLEN_, D_, H_, H_, CLEN_,
                  nullptr, 0, B_ * NH_, NH_,
                  (long long)QLEN_ * H_, D_,
                  (long long)CLEN_ * H_, D_,
                  (long long)NH_ * QLEN_ * CLEN_, (long long)QLEN_ * CLEN_);

        launch_bf(true, S.qph, S.qpl, S.rh, S.rl,
                  S.bd, nullptr, nullptr,
                  QLEN_, RLEN_, D_, H_, H_, RLEN_,
                  nullptr, 0, B_ * NH_, NH_,
                  (long long)QLEN_ * H_, D_,
                  (long long)RLEN_ * H_, D_,
                  (long long)NH_ * QLEN_ * RLEN_, (long long)QLEN_ * RLEN_);

        score_softmax_kernel<<<B_ * NH_ * QLEN_, 256>>>(mask, seg);

        launch_bf(false, S.ph, S.pl, S.vh, S.vl,
                  nullptr, S.ath, S.atl,
                  QLEN_, D_, CLEN_, CLEN_, H_, H_,
                  nullptr, 0, B_ * NH_, NH_,
                  (long long)NH_ * QLEN_ * CLEN_, (long long)QLEN_ * CLEN_,
                  (long long)CLEN_ * H_, D_,
                  (long long)QLEN_ * H_, D_,
                  /*tn64=*/true);

        launch_bf(true, S.ath, S.atl, S.woh + wofs, S.wol + wofs,
                  S.ao, nullptr, nullptr, rowsQ, H_, H_, H_, H_, H_,
                  nullptr, 0, 1, 1, 0,0,0,0,0,0);

        ln_kernel<<<rowsQ, 256>>>(S.ao, x, ln1_g + l * H_, ln1_b + l * H_,
                                  S.y, S.yh, S.yl);

        launch_bf(false, S.yh, S.yl, S.f1h + (long long)l * H_ * F_, S.f1l + (long long)l * H_ * F_,
                  nullptr, S.mih, S.mil, rowsQ, F_, H_, H_, F_, F_,
                  ffn_b1 + (long long)l * F_, 1, 1, 1, 0,0,0,0,0,0);
        launch_bf(false, S.mih, S.mil, S.f2h + (long long)l * F_ * H_, S.f2l + (long long)l * F_ * H_,
                  S.ao, nullptr, nullptr, rowsQ, H_, F_, F_, H_, H_,
                  ffn_b2 + (long long)l * H_, 0, 1, 1, 0,0,0,0,0,0);

        float* xout = (l == L_ - 1) ? (float*)d_out : S.x;
        ln_kernel<<<rowsQ, 256>>>(S.ao, S.y, ln2_g + l * H_, ln2_b + l * H_,
                                  xout, S.xh, S.xl);

        x = S.x;
    }
}

// round 11
// speedup vs baseline: 3.3351x; 1.2293x over previous
#include <cuda_runtime.h>
#include <cuda_bf16.h>
#include <math.h>

// ---------------- problem constants ----------------
#define L_    4
#define B_    2
#define QLEN_ 512
#define MLEN_ 512
#define CLEN_ 1024
#define RLEN_ 1536
#define H_    1024
#define NH_   16
#define D_    64
#define F_    4096
#define LN_EPS_ 1e-12f

#define EFSTRIDE ((long long)B_*NH_*QLEN_)
#define PADE 1024

typedef __nv_bfloat16 bf16;
typedef __nv_bfloat162 bf162;

// ---------------- fp32 scratch ----------------
__device__ float g_x  [B_*QLEN_*H_];
__device__ float g_q  [B_*QLEN_*H_];
__device__ float g_sc [(long long)B_*NH_*QLEN_*CLEN_];
__device__ float g_bd [(long long)B_*NH_*QLEN_*RLEN_];
__device__ float g_ef [2*B_*NH_*QLEN_];
__device__ float g_ao [B_*QLEN_*H_];
__device__ float g_y  [B_*QLEN_*H_];
__device__ int   g_segmode;

// ---------------- bf16 hi/lo split scratch ----------------
__device__ bf16 g_xh [B_*QLEN_*H_+PADE],  g_xl [B_*QLEN_*H_+PADE];
__device__ bf16 g_cth[B_*CLEN_*H_+PADE],  g_ctl[B_*CLEN_*H_+PADE];
__device__ bf16 g_peh[B_*RLEN_*H_+PADE],  g_pel[B_*RLEN_*H_+PADE];
__device__ bf16 g_qch[B_*QLEN_*H_+PADE],  g_qcl[B_*QLEN_*H_+PADE];
__device__ bf16 g_qph[B_*QLEN_*H_+PADE],  g_qpl[B_*QLEN_*H_+PADE];
__device__ bf16 g_kh [B_*CLEN_*H_+PADE],  g_kl [B_*CLEN_*H_+PADE];
__device__ bf16 g_vh [B_*CLEN_*H_+PADE],  g_vl [B_*CLEN_*H_+PADE];
__device__ bf16 g_rh [B_*RLEN_*H_+PADE],  g_rl [B_*RLEN_*H_+PADE];
__device__ bf16 g_ph [(long long)B_*NH_*QLEN_*CLEN_+PADE], g_pl[(long long)B_*NH_*QLEN_*CLEN_+PADE];
__device__ bf16 g_ath[B_*QLEN_*H_+PADE],  g_atl[B_*QLEN_*H_+PADE];
__device__ bf16 g_yh [B_*QLEN_*H_+PADE],  g_yl [B_*QLEN_*H_+PADE];
__device__ bf16 g_mih[B_*QLEN_*F_+PADE],  g_mil[B_*QLEN_*F_+PADE];
// weights
__device__ bf16 g_wqh[L_*H_*H_+PADE], g_wql[L_*H_*H_+PADE];
__device__ bf16 g_wkh[L_*H_*H_+PADE], g_wkl[L_*H_*H_+PADE];
__device__ bf16 g_wvh[L_*H_*H_+PADE], g_wvl[L_*H_*H_+PADE];
__device__ bf16 g_wrh[L_*H_*H_+PADE], g_wrl[L_*H_*H_+PADE];
__device__ bf16 g_woh[L_*H_*H_+PADE], g_wol[L_*H_*H_+PADE];
__device__ bf16 g_f1h[L_*H_*F_+PADE], g_f1l[L_*H_*F_+PADE];
__device__ bf16 g_f2h[L_*F_*H_+PADE], g_f2l[L_*F_*H_+PADE];

__device__ __forceinline__ void split1(float v, bf16& h, bf16& l) {
    h = __float2bfloat16(v);
    l = __float2bfloat16(v - __bfloat162float(h));
}

// ---------------- tensor-core GEMM: pre-split bf16 hi/lo, cp.async, 512 threads ----
// C[M,N] = A[M,K]*B ; TB=0: B is [K,N]; TB=1: B is [N,K] (C=A*B^T).
// 128xTN_ tile, 16 warps (4m x 4n), warp tile 32 x (TN_/4).
// 3 stages of k=32; two 16-k ldmatrix/MMA passes per stage.
// Split product: AhBh + AhBl + AlBh, fp32 accumulate.
#define TM 128
#define ASTR32 40           // halfs per 32-k row (32 data + 8 pad) = 80B
#define STAGES_ 3
#define A_ST32 (128*ASTR32) // halfs per A component per stage

__device__ __forceinline__ unsigned smaddr(const void* p) {
    return (unsigned)__cvta_generic_to_shared(p);
}

#define CPA16(dst, src) asm volatile( \
    "cp.async.ca.shared.global [%0], [%1], 16;" :: "r"(dst), "l"(src))
#define CP_COMMIT() asm volatile("cp.async.commit_group;")
#define CP_WAIT1()  asm volatile("cp.async.wait_group 1;")

#define LDSM_X4(r, a) asm volatile( \
    "ldmatrix.sync.aligned.m8n8.x4.shared.b16 {%0,%1,%2,%3}, [%4];" \
    : "=r"((r)[0]), "=r"((r)[1]), "=r"((r)[2]), "=r"((r)[3]) : "r"(a))
#define LDSM_X2(r, a) asm volatile( \
    "ldmatrix.sync.aligned.m8n8.x2.shared.b16 {%0,%1}, [%2];" \
    : "=r"((r)[0]), "=r"((r)[1]) : "r"(a))
#define LDSM_X2T(r, a) asm volatile( \
    "ldmatrix.sync.aligned.m8n8.x2.trans.shared.b16 {%0,%1}, [%2];" \
    : "=r"((r)[0]), "=r"((r)[1]) : "r"(a))
#define MMA_BF16(c, a, b) asm volatile( \
    "mma.sync.aligned.m16n8k16.row.col.f32.bf16.bf16.f32 " \
    "{%0,%1,%2,%3}, {%4,%5,%6,%7}, {%8,%9}, {%0,%1,%2,%3};" \
    : "+f"((c)[0]), "+f"((c)[1]), "+f"((c)[2]), "+f"((c)[3]) \
    : "r"((a)[0]), "r"((a)[1]), "r"((a)[2]), "r"((a)[3]), "r"((b)[0]), "r"((b)[1]))

template<int TB, int TN_>
__global__ void __launch_bounds__(512)
gemm_bf(const bf16* __restrict__ Ah, const bf16* __restrict__ Al,
        const bf16* __restrict__ Bh, const bf16* __restrict__ Bl,
        float* __restrict__ C, bf16* __restrict__ Ch, bf16* __restrict__ Cl,
        int M, int N, int K, int lda, int ldb, int ldc,
        const float* __restrict__ bias, int relu,
        int inner,
        long long oAo, long long oAi, long long oBo, long long oBi,
        long long oCo, long long oCi)
{
    constexpr int WN   = TN_ / 4;                  // warp n-width (32 or 16)
    constexpr int NF   = WN / 8;                   // n-fragments per warp (4 or 2)
    constexpr int BSTR = TN_ + 8;                  // TB=0 row stride (halfs)
    constexpr int BS   = (TB == 0) ? (32 * BSTR) : A_ST32;

    int z  = blockIdx.z;
    int zo = z / inner;
    int zi = z - zo * inner;
    Ah += zo * oAo + zi * oAi;
    Al += zo * oAo + zi * oAi;
    Bh += zo * oBo + zi * oBi;
    Bl += zo * oBo + zi * oBi;
    long long cofs = zo * oCo + zi * oCi;
    if (C)  C  += cofs;
    if (Ch) { Ch += cofs; Cl += cofs; }

    extern __shared__ __align__(16) unsigned char dsm_raw[];
    bf16* sAp = reinterpret_cast<bf16*>(dsm_raw);          // [STAGES][2][A_ST32]
    bf16* sBp = sAp + STAGES_ * 2 * A_ST32;                // [STAGES][2][BS]

    const int t    = threadIdx.x;
    const int lane = t & 31;
    const int warp = t >> 5;          // 0..15
    const int m0 = blockIdx.y * TM;
    const int n0 = blockIdx.x * TN_;
    const int wm = (warp & 3) * 32;   // warp tile: 32 rows x WN cols
    const int wn = (warp >> 2) * WN;

    float acc[2][NF][4];
#pragma unroll
    for (int mf = 0; mf < 2; mf++)
#pragma unroll
        for (int nf = 0; nf < NF; nf++)
#pragma unroll
            for (int e = 0; e < 4; e++) acc[mf][nf][e] = 0.f;

    // loader coords (512 threads)
    const int ar  = t >> 2;           // 0..127 (A rows; TB=1 B rows)
    const int ak8 = (t & 3) * 8;      // 4 chunks of 8 halfs across 32-k
    const int b0r = t >> 4;           // 0..31 (TB=0 TN128 k-rows)
    const int b0c = (t & 15) * 8;
    const int b4r = (t & 255) >> 3;   // 0..31 (TB=0 TN64, half threads)
    const int b4c = (t & 7) * 8;

    auto issue = [&](int st, int k0) {
        {
            unsigned d = smaddr(sAp + (st * 2) * A_ST32 + ar * ASTR32 + ak8);
            CPA16(d, Ah + (long long)(m0 + ar) * lda + k0 + ak8);
            CPA16(d + A_ST32 * 2, Al + (long long)(m0 + ar) * lda + k0 + ak8);
        }
        if (TB == 0) {
            if (TN_ == 128) {
                unsigned d = smaddr(sBp + (st * 2) * BS + b0r * BSTR + b0c);
                CPA16(d, Bh + (long long)(k0 + b0r) * ldb + n0 + b0c);
                CPA16(d + BS * 2, Bl + (long long)(k0 + b0r) * ldb + n0 + b0c);
            } else if (t < 256) {
                unsigned d = smaddr(sBp + (st * 2) * BS + b4r * BSTR + b4c);
                CPA16(d, Bh + (long long)(k0 + b4r) * ldb + n0 + b4c);
                CPA16(d + BS * 2, Bl + (long long)(k0 + b4r) * ldb + n0 + b4c);
            }
        } else {
            unsigned d = smaddr(sBp + (st * 2) * BS + ar * ASTR32 + ak8);
            CPA16(d, Bh + (long long)(n0 + ar) * ldb + k0 + ak8);
            CPA16(d + BS * 2, Bl + (long long)(n0 + ar) * ldb + k0 + ak8);
        }
        CP_COMMIT();
    };

    auto compute = [&](int st) {
        bf16* A0 = sAp + (st * 2) * A_ST32;
        bf16* B0 = sBp + (st * 2) * BS;
#pragma unroll
        for (int p = 0; p < 2; p++) {
            unsigned aHi = smaddr(A0 + (wm + (lane & 15)) * ASTR32 + p * 16 + (lane >> 4) * 8);
            unsigned aLo = aHi + A_ST32 * 2;
            unsigned bHi = (TB == 0)
                ? smaddr(B0 + (p * 16 + (lane & 15)) * BSTR + wn)
                : smaddr(B0 + (wn + (lane & 7)) * ASTR32 + p * 16 + ((lane >> 3) & 1) * 8);
            unsigned bLo = bHi + BS * 2;

            unsigned ah[2][4], bh[NF][2], bl[NF][2];
#pragma unroll
            for (int mf = 0; mf < 2; mf++) LDSM_X4(ah[mf], aHi + mf * (16 * ASTR32 * 2));
#pragma unroll
            for (int nf = 0; nf < NF; nf++) {
                if (TB == 0) {
                    LDSM_X2T(bh[nf], bHi + nf * 16);
                    LDSM_X2T(bl[nf], bLo + nf * 16);
                } else {
                    LDSM_X2(bh[nf], bHi + nf * (8 * ASTR32 * 2));
                    LDSM_X2(bl[nf], bLo + nf * (8 * ASTR32 * 2));
                }
            }
#pragma unroll
            for (int mf = 0; mf < 2; mf++)
#pragma unroll
                for (int nf = 0; nf < NF; nf++)
                    MMA_BF16(acc[mf][nf], ah[mf], bh[nf]);
#pragma unroll
            for (int mf = 0; mf < 2; mf++)
#pragma unroll
                for (int nf = 0; nf < NF; nf++)
                    MMA_BF16(acc[mf][nf], ah[mf], bl[nf]);
#pragma unroll
            for (int mf = 0; mf < 2; mf++) LDSM_X4(ah[mf], aLo + mf * (16 * ASTR32 * 2));
#pragma unroll
            for (int mf = 0; mf < 2; mf++)
#pragma unroll
                for (int nf = 0; nf < NF; nf++)
                    MMA_BF16(acc[mf][nf], ah[mf], bh[nf]);
        }
    };

    const int kT = K / 32;
    int issued = 0;
    for (; issued < STAGES_ - 1 && issued < kT; issued++) issue(issued, issued * 32);

    for (int i = 0; i < kT; i++) {
        CP_WAIT1();
        __syncthreads();
        compute(i % STAGES_);
        if (issued < kT) { issue(issued % STAGES_, issued * 32); issued++; }
        else             { CP_COMMIT(); }
    }

    // epilogue
    const int er = lane >> 2;
    const int ec = (lane & 3) * 2;
#pragma unroll
    for (int mf = 0; mf < 2; mf++) {
#pragma unroll
        for (int nf = 0; nf < NF; nf++) {
            int gm = m0 + wm + mf * 16 + er;
            int gn = n0 + wn + nf * 8 + ec;
#pragma unroll
            for (int half = 0; half < 2; half++) {
                int rm = gm + half * 8;
                if (rm >= M) continue;
                float v0 = acc[mf][nf][half * 2 + 0];
                float v1 = acc[mf][nf][half * 2 + 1];
                if (bias) { if (gn < N) v0 += bias[gn]; if (gn + 1 < N) v1 += bias[gn + 1]; }
                if (relu) { v0 = fmaxf(v0, 0.f); v1 = fmaxf(v1, 0.f); }
                if (gn < N) {
                    if (C) {
                        C[(long long)rm * ldc + gn] = v0;
                        if (gn + 1 < N) C[(long long)rm * ldc + gn + 1] = v1;
                    }
                    if (Ch && gn + 1 < N) {
                        bf16 h0, l0, h1, l1;
                        split1(v0, h0, l0); split1(v1, h1, l1);
                        bf162 hp; hp.x = h0; hp.y = h1;
                        bf162 lp; lp.x = l0; lp.y = l1;
                        *reinterpret_cast<bf162*>(&Ch[(long long)rm * ldc + gn]) = hp;
                        *reinterpret_cast<bf162*>(&Cl[(long long)rm * ldc + gn]) = lp;
                    }
                }
            }
        }
    }
}

static inline int smem_bytes(int tb, int tn) {
    int bs = (tb == 0) ? 32 * (tn + 8) : A_ST32;
    return STAGES_ * 2 * (A_ST32 + bs) * 2;
}

static void launch_bf(bool transB,
                      const bf16* Ah, const bf16* Al,
                      const bf16* Bh, const bf16* Bl,
                      float* C, bf16* Ch, bf16* Cl,
                      int M, int N, int K, int lda, int ldb, int ldc,
                      const float* bias, int relu,
                      int batches, int inner,
                      long long oAo, long long oAi,
                      long long oBo, long long oBi,
                      long long oCo, long long oCi,
                      bool tn64 = false)
{
    int tn = tn64 ? 64 : 128;
    dim3 grid((N + tn - 1) / tn, (M + TM - 1) / TM, batches);
    int sm = smem_bytes(transB ? 1 : 0, tn);
    if (transB) {
        if (tn64)
            gemm_bf<1,64><<<grid, 512, sm>>>(Ah, Al, Bh, Bl, C, Ch, Cl, M, N, K, lda, ldb, ldc,
                                             bias, relu, inner, oAo, oAi, oBo, oBi, oCo, oCi);
        else
            gemm_bf<1,128><<<grid, 512, sm>>>(Ah, Al, Bh, Bl, C, Ch, Cl, M, N, K, lda, ldb, ldc,
                                              bias, relu, inner, oAo, oAi, oBo, oBi, oCo, oCi);
    } else {
        if (tn64)
            gemm_bf<0,64><<<grid, 512, sm>>>(Ah, Al, Bh, Bl, C, Ch, Cl, M, N, K, lda, ldb, ldc,
                                             bias, relu, inner, oAo, oAi, oBo, oBi, oCo, oCi);
        else
            gemm_bf<0,128><<<grid, 512, sm>>>(Ah, Al, Bh, Bl, C, Ch, Cl, M, N, K, lda, ldb, ldc,
                                              bias, relu, inner, oAo, oAi, oBo, oBi, oCo, oCi);
    }
}

// ---------------- split conversion (fp32 -> bf16 hi/lo) ----------------
__global__ void split_kernel(const float4* __restrict__ src,
                             bf162* __restrict__ h, bf162* __restrict__ l, int n4)
{
    int i = blockIdx.x * blockDim.x + threadIdx.x;
    if (i >= n4) return;
    float4 v = src[i];
    bf16 h0, l0, h1, l1, h2, l2, h3, l3;
    split1(v.x, h0, l0); split1(v.y, h1, l1);
    split1(v.z, h2, l2); split1(v.w, h3, l3);
    bf162 a; a.x = h0; a.y = h1;
    bf162 b; b.x = h2; b.y = h3;
    h[2 * i] = a; h[2 * i + 1] = b;
    a.x = l0; a.y = l1; b.x = l2; b.y = l3;
    l[2 * i] = a; l[2 * i + 1] = b;
}
static void launch_split(const float* src, bf16* h, bf16* l, long long n)
{
    int n4 = (int)(n / 4);
    split_kernel<<<(n4 + 255) / 256, 256>>>(
        (const float4*)src, (bf162*)h, (bf162*)l, n4);
}

// ---------------- small kernels ----------------
__global__ void detect_seg_kernel(const unsigned char* __restrict__ p)
{
    if (threadIdx.x == 0 && blockIdx.x == 0) {
        bool f32 = false, nonalign = false;
        for (int i = 0; i < 1024; i++) {
            unsigned char c = p[i];
            if ((i & 3) == 3 && c == 0x3F) f32 = true;
            if ((i & 3) != 0 && c == 1)    nonalign = true;
        }
        g_segmode = f32 ? 0 : (nonalign ? 2 : 1);
    }
}

__global__ void build_ctx_kernel(const float* __restrict__ mems_l,
                                 const float* __restrict__ x)
{
    int idx = blockIdx.x * blockDim.x + threadIdx.x;
    if (idx >= B_ * CLEN_ * H_) return;
    int h = idx % H_;
    int j = (idx / H_) % CLEN_;
    int b = idx / (H_ * CLEN_);
    float v = (j < MLEN_) ? mems_l[((long long)b * MLEN_ + j) * H_ + h]
                          : x[((long long)b * QLEN_ + (j - MLEN_)) * H_ + h];
    bf16 hh, ll; split1(v, hh, ll);
    g_cth[idx] = hh; g_ctl[idx] = ll;
}

__global__ void make_qcp_kernel(const float* __restrict__ cb,
                                const float* __restrict__ pb)
{
    int idx = blockIdx.x * blockDim.x + threadIdx.x;
    if (idx >= B_ * QLEN_ * H_) return;
    int nd  = idx % H_;
    float q = g_q[idx];
    bf16 hh, ll;
    split1(q + cb[nd], hh, ll); g_qch[idx] = hh; g_qcl[idx] = ll;
    split1(q + pb[nd], hh, ll); g_qph[idx] = hh; g_qpl[idx] = ll;
}

__global__ void ef_kernel(const float* __restrict__ sb,
                          const float* __restrict__ se_l)
{
    int bi   = blockIdx.x;
    int n    = threadIdx.x >> 5;
    int lane = threadIdx.x & 31;
    const float* qrow = g_q + (long long)bi * H_ + n * D_;
    float s0 = 0.f, s1 = 0.f;
#pragma unroll
    for (int d = lane; d < D_; d += 32) {
        float qv = qrow[d] + sb[n * D_ + d];
        s0 += qv * se_l[n * D_ + d];
        s1 += qv * se_l[NH_ * D_ + n * D_ + d];
    }
#pragma unroll
    for (int o = 16; o > 0; o >>= 1) {
        s0 += __shfl_down_sync(0xFFFFFFFFu, s0, o);
        s1 += __shfl_down_sync(0xFFFFFFFFu, s1, o);
    }
    if (lane == 0) {
        int b = bi / QLEN_;
        int i = bi - b * QLEN_;
        long long ridx = ((long long)(b * NH_ + n) * QLEN_ + i);
        g_ef[ridx]            = s0;
        g_ef[EFSTRIDE + ridx] = s1;
    }
}

__global__ void __launch_bounds__(256)
score_softmax_kernel(const float* __restrict__ mask, const void* __restrict__ seg)
{
    int row = blockIdx.x;
    int i   = row % QLEN_;
    int bn  = row / QLEN_;
    int b   = bn / NH_;
    int tid = threadIdx.x;

    long long rbase = (long long)bn * QLEN_ * CLEN_ + (long long)i * CLEN_;
    const float* ac   = g_sc + rbase;
    const float* bd   = g_bd + (long long)bn * QLEN_ * RLEN_ + (long long)i * RLEN_ + (QLEN_ - i);
    const float* mrow = mask + ((long long)b * QLEN_ + i) * CLEN_;
    long long    sbase = ((long long)b * QLEN_ + i) * (long long)CLEN_;
    float ef0 = g_ef[(long long)bn * QLEN_ + i];
    float ef1 = g_ef[EFSTRIDE + (long long)bn * QLEN_ + i];
    int mode = g_segmode;
    const float rs = 0.125f;

    float vals[4];
    float lmax = -3.0e38f;
#pragma unroll
    for (int u = 0; u < 4; u++) {
        int j = u * 256 + tid;
        bool s;
        if (mode == 2)      s = ((const unsigned char*)seg)[sbase + j] != 0;
        else if (mode == 1) s = ((const int*)seg)[sbase + j] != 0;
        else                s = ((const float*)seg)[sbase + j] != 0.f;
        float ef = s ? ef1 : ef0;
        float sc = (ac[j] + bd[j] + ef) * rs + mrow[j] * (-1e30f);
        vals[u] = sc;
        lmax = fmaxf(lmax, sc);
    }

    __shared__ float red[256];
    red[tid] = lmax;
    __syncthreads();
    for (int o = 128; o > 0; o >>= 1) {
        if (tid < o) red[tid] = fmaxf(red[tid], red[tid + o]);
        __syncthreads();
    }
    float m = red[0];
    __syncthreads();

    float lsum = 0.f;
#pragma unroll
    for (int u = 0; u < 4; u++) {
        vals[u] = __expf(vals[u] - m);
        lsum += vals[u];
    }
    red[tid] = lsum;
    __syncthreads();
    for (int o = 128; o > 0; o >>= 1) {
        if (tid < o) red[tid] += red[tid + o];
        __syncthreads();
    }
    float inv = 1.f / red[0];
#pragma unroll
    for (int u = 0; u < 4; u++) {
        int j = u * 256 + tid;
        bf16 hh, ll; split1(vals[u] * inv, hh, ll);
        g_ph[rbase + j] = hh;
        g_pl[rbase + j] = ll;
    }
}

__global__ void __launch_bounds__(256)
ln_kernel(const float* __restrict__ a, const float* __restrict__ b,
          const float* __restrict__ gamma, const float* __restrict__ beta,
          float* __restrict__ out, bf16* __restrict__ oh, bf16* __restrict__ ol)
{
    int row = blockIdx.x;
    int tid = threadIdx.x;
    const float* pa = a + (long long)row * H_;
    const float* pb = b + (long long)row * H_;

    float v[4];
    float lsum = 0.f;
#pragma unroll
    for (int u = 0; u < 4; u++) {
        int j = u * 256 + tid;
        v[u] = pa[j] + pb[j];
        lsum += v[u];
    }
    __shared__ float red[256];
    red[tid] = lsum;
    __syncthreads();
    for (int o = 128; o > 0; o >>= 1) {
        if (tid < o) red[tid] += red[tid + o];
        __syncthreads();
    }
    float mu = red[0] * (1.0f / H_);
    __syncthreads();

    float lvar = 0.f;
#pragma unroll
    for (int u = 0; u < 4; u++) {
        float d = v[u] - mu;
        lvar += d * d;
    }
    red[tid] = lvar;
    __syncthreads();
    for (int o = 128; o > 0; o >>= 1) {
        if (tid < o) red[tid] += red[tid + o];
        __syncthreads();
    }
    float rstd = rsqrtf(red[0] * (1.0f / H_) + LN_EPS_);
    float* po = out + (long long)row * H_;
#pragma unroll
    for (int u = 0; u < 4; u++) {
        int j = u * 256 + tid;
        float val = (v[u] - mu) * rstd * gamma[j] + beta[j];
        po[j] = val;
        if (oh) {
            bf16 hh, ll; split1(val, hh, ll);
            oh[(long long)row * H_ + j] = hh;
            ol[(long long)row * H_ + j] = ll;
        }
    }
}

// ---------------- host orchestration ----------------
struct Ptrs {
    float *x, *q, *sc, *bd, *ao, *y;
    bf16 *xh,*xl,*cth,*ctl,*peh,*pel,*qch,*qcl,*qph,*qpl,*kh,*kl,*vh,*vl,*rh,*rl,
         *ph,*pl,*ath,*atl,*yh,*yl,*mih,*mil,
         *wqh,*wql,*wkh,*wkl,*wvh,*wvl,*wrh,*wrl,*woh,*wol,*f1h,*f1l,*f2h,*f2l;
    bool init = false;
};

extern "C" void kernel_launch(void* const* d_in, const int* in_sizes, int n_in,
                              void* d_out, int out_size)
{
    (void)in_sizes; (void)n_in; (void)out_size;

    const float* content   = (const float*)d_in[0];
    const float* mask      = (const float*)d_in[1];
    const float* posenc    = (const float*)d_in[2];
    const void*  seg       = d_in[3];
    const float* mems      = (const float*)d_in[4];
    const float* w_q       = (const float*)d_in[5];
    const float* w_k       = (const float*)d_in[6];
    const float* w_v       = (const float*)d_in[7];
    const float* w_r       = (const float*)d_in[8];
    const float* w_o       = (const float*)d_in[9];
    const float* ffn_w1    = (const float*)d_in[10];
    const float* ffn_b1    = (const float*)d_in[11];
    const float* ffn_w2    = (const float*)d_in[12];
    const float* ffn_b2    = (const float*)d_in[13];
    const float* ln1_g     = (const float*)d_in[14];
    const float* ln1_b     = (const float*)d_in[15];
    const float* ln2_g     = (const float*)d_in[16];
    const float* ln2_b     = (const float*)d_in[17];
    const float* cbias     = (const float*)d_in[18];
    const float* pbias     = (const float*)d_in[19];
    const float* sbias     = (const float*)d_in[20];
    const float* segenc    = (const float*)d_in[21];

    static Ptrs S;
    if (!S.init) {
        cudaGetSymbolAddress((void**)&S.x,  g_x);   cudaGetSymbolAddress((void**)&S.q,  g_q);
        cudaGetSymbolAddress((void**)&S.sc, g_sc);  cudaGetSymbolAddress((void**)&S.bd, g_bd);
        cudaGetSymbolAddress((void**)&S.ao, g_ao);  cudaGetSymbolAddress((void**)&S.y,  g_y);
        cudaGetSymbolAddress((void**)&S.xh, g_xh);  cudaGetSymbolAddress((void**)&S.xl, g_xl);
        cudaGetSymbolAddress((void**)&S.cth,g_cth); cudaGetSymbolAddress((void**)&S.ctl,g_ctl);
        cudaGetSymbolAddress((void**)&S.peh,g_peh); cudaGetSymbolAddress((void**)&S.pel,g_pel);
        cudaGetSymbolAddress((void**)&S.qch,g_qch); cudaGetSymbolAddress((void**)&S.qcl,g_qcl);
        cudaGetSymbolAddress((void**)&S.qph,g_qph); cudaGetSymbolAddress((void**)&S.qpl,g_qpl);
        cudaGetSymbolAddress((void**)&S.kh, g_kh);  cudaGetSymbolAddress((void**)&S.kl, g_kl);
        cudaGetSymbolAddress((void**)&S.vh, g_vh);  cudaGetSymbolAddress((void**)&S.vl, g_vl);
        cudaGetSymbolAddress((void**)&S.rh, g_rh);  cudaGetSymbolAddress((void**)&S.rl, g_rl);
        cudaGetSymbolAddress((void**)&S.ph, g_ph);  cudaGetSymbolAddress((void**)&S.pl, g_pl);
        cudaGetSymbolAddress((void**)&S.ath,g_ath); cudaGetSymbolAddress((void**)&S.atl,g_atl);
        cudaGetSymbolAddress((void**)&S.yh, g_yh);  cudaGetSymbolAddress((void**)&S.yl, g_yl);
        cudaGetSymbolAddress((void**)&S.mih,g_mih); cudaGetSymbolAddress((void**)&S.mil,g_mil);
        cudaGetSymbolAddress((void**)&S.wqh,g_wqh); cudaGetSymbolAddress((void**)&S.wql,g_wql);
        cudaGetSymbolAddress((void**)&S.wkh,g_wkh); cudaGetSymbolAddress((void**)&S.wkl,g_wkl);
        cudaGetSymbolAddress((void**)&S.wvh,g_wvh); cudaGetSymbolAddress((void**)&S.wvl,g_wvl);
        cudaGetSymbolAddress((void**)&S.wrh,g_wrh); cudaGetSymbolAddress((void**)&S.wrl,g_wrl);
        cudaGetSymbolAddress((void**)&S.woh,g_woh); cudaGetSymbolAddress((void**)&S.wol,g_wol);
        cudaGetSymbolAddress((void**)&S.f1h,g_f1h); cudaGetSymbolAddress((void**)&S.f1l,g_f1l);
        cudaGetSymbolAddress((void**)&S.f2h,g_f2h); cudaGetSymbolAddress((void**)&S.f2l,g_f2l);
        cudaFuncSetAttribute((const void*)gemm_bf<0,128>,
            cudaFuncAttributeMaxDynamicSharedMemorySize, smem_bytes(0,128));
        cudaFuncSetAttribute((const void*)gemm_bf<1,128>,
            cudaFuncAttributeMaxDynamicSharedMemorySize, smem_bytes(1,128));
        cudaFuncSetAttribute((const void*)gemm_bf<0,64>,
            cudaFuncAttributeMaxDynamicSharedMemorySize, smem_bytes(0,64));
        cudaFuncSetAttribute((const void*)gemm_bf<1,64>,
            cudaFuncAttributeMaxDynamicSharedMemorySize, smem_bytes(1,64));
        S.init = true;
    }

    detect_seg_kernel<<<1, 32>>>((const unsigned char*)seg);

    launch_split(content, S.xh, S.xl, (long long)B_*QLEN_*H_);
    launch_split(posenc,  S.peh, S.pel, (long long)B_*RLEN_*H_);
    launch_split(w_q, S.wqh, S.wql, (long long)L_*H_*H_);
    launch_split(w_k, S.wkh, S.wkl, (long long)L_*H_*H_);
    launch_split(w_v, S.wvh, S.wvl, (long long)L_*H_*H_);
    launch_split(w_r, S.wrh, S.wrl, (long long)L_*H_*H_);
    launch_split(w_o, S.woh, S.wol, (long long)L_*H_*H_);
    launch_split(ffn_w1, S.f1h, S.f1l, (long long)L_*H_*F_);
    launch_split(ffn_w2, S.f2h, S.f2l, (long long)L_*F_*H_);

    const float* x = content;
    const int rowsQ = B_ * QLEN_;
    const int rowsC = B_ * CLEN_;
    const int rowsR = B_ * RLEN_;

    for (int l = 0; l < L_; l++) {
        long long wofs = (long long)l * H_ * H_;

        {
            int total = B_ * CLEN_ * H_;
            build_ctx_kernel<<<(total + 255) / 256, 256>>>(
                mems + (long long)l * B_ * MLEN_ * H_, x);
        }

        // q proj (TN=64 -> 128 CTAs)
        launch_bf(false, S.xh, S.xl, S.wqh + wofs, S.wql + wofs,
                  S.q, nullptr, nullptr, rowsQ, H_, H_, H_, H_, H_,
                  nullptr, 0, 1, 1, 0,0,0,0,0,0, /*tn64=*/true);
        launch_bf(false, S.cth, S.ctl, S.wkh + wofs, S.wkl + wofs,
                  nullptr, S.kh, S.kl, rowsC, H_, H_, H_, H_, H_,
                  nullptr, 0, 1, 1, 0,0,0,0,0,0);
        launch_bf(false, S.cth, S.ctl, S.wvh + wofs, S.wvl + wofs,
                  nullptr, S.vh, S.vl, rowsC, H_, H_, H_, H_, H_,
                  nullptr, 0, 1, 1, 0,0,0,0,0,0);
        launch_bf(false, S.peh, S.pel, S.wrh + wofs, S.wrl + wofs,
                  nullptr, S.rh, S.rl, rowsR, H_, H_, H_, H_, H_,
                  nullptr, 0, 1, 1, 0,0,0,0,0,0);

        {
            int total = B_ * QLEN_ * H_;
            make_qcp_kernel<<<(total + 255) / 256, 256>>>(cbias, pbias);
        }
        ef_kernel<<<B_ * QLEN_, 512>>>(sbias, segenc + (long long)l * 2 * NH_ * D_);

        launch_bf(true, S.qch, S.qcl, S.kh, S.kl,
                  S.sc, nullptr, nullptr,
                  QLEN_, CLEN_, D_, H_, H_, CLEN_,
                  nullptr, 0, B_ * NH_, NH_,
                  (long long)QLEN_ * H_, D_,
                  (long long)CLEN_ * H_, D_,
                  (long long)NH_ * QLEN_ * CLEN_, (long long)QLEN_ * CLEN_);

        launch_bf(true, S.qph, S.qpl, S.rh, S.rl,
                  S.bd, nullptr, nullptr,
                  QLEN_, RLEN_, D_, H_, H_, RLEN_,
                  nullptr, 0, B_ * NH_, NH_,
                  (long long)QLEN_ * H_, D_,
                  (long long)RLEN_ * H_, D_,
                  (long long)NH_ * QLEN_ * RLEN_, (long long)QLEN_ * RLEN_);

        score_softmax_kernel<<<B_ * NH_ * QLEN_, 256>>>(mask, seg);

        launch_bf(false, S.ph, S.pl, S.vh, S.vl,
                  nullptr, S.ath, S.atl,
                  QLEN_, D_, CLEN_, CLEN_, H_, H_,
                  nullptr, 0, B_ * NH_, NH_,
                  (long long)NH_ * QLEN_ * CLEN_, (long long)QLEN_ * CLEN_,
                  (long long)CLEN_ * H_, D_,
                  (long long)QLEN_ * H_, D_,
                  /*tn64=*/true);

        // out proj (TN=64 -> 128 CTAs)
        launch_bf(true, S.ath, S.atl, S.woh + wofs, S.wol + wofs,
                  S.ao, nullptr, nullptr, rowsQ, H_, H_, H_, H_, H_,
                  nullptr, 0, 1, 1, 0,0,0,0,0,0, /*tn64=*/true);

        ln_kernel<<<rowsQ, 256>>>(S.ao, x, ln1_g + l * H_, ln1_b + l * H_,
                                  S.y, S.yh, S.yl);

        launch_bf(false, S.yh, S.yl, S.f1h + (long long)l * H_ * F_, S.f1l + (long long)l * H_ * F_,
                  nullptr, S.mih, S.mil, rowsQ, F_, H_, H_, F_, F_,
                  ffn_b1 + (long long)l * F_, 1, 1, 1, 0,0,0,0,0,0);
        // ffn2 (TN=64 -> 128 CTAs)
        launch_bf(false, S.mih, S.mil, S.f2h + (long long)l * F_ * H_, S.f2l + (long long)l * F_ * H_,
                  S.ao, nullptr, nullptr, rowsQ, H_, F_, F_, H_, H_,
                  ffn_b2 + (long long)l * H_, 0, 1, 1, 0,0,0,0,0,0, /*tn64=*/true);

        float* xout = (l == L_ - 1) ? (float*)d_out : S.x;
        ln_kernel<<<rowsQ, 256>>>(S.ao, S.y, ln2_g + l * H_, ln2_b + l * H_,
                                  xout, S.xh, S.xl);

        x = S.x;
    }
}